// round 11
// baseline (speedup 1.0000x reference)
#include <cuda_runtime.h>
#include <cuda_bf16.h>
#include <cstdint>

// Problem constants
#define BB   2
#define TT   4096
#define DD   512
#define HH   8
#define DHH  64
#define MTOT (BB*TT)          // 8192
#define WSZ  (DD*DD)

// Scratch (allocation-free __device__ globals)
__device__ float g_Q[BB*HH*TT*DHH];                 // (bh, t, dh) fp32
__device__ __nv_bfloat16 g_Kh[BB*HH*TT*DHH];        // (bh, t, dh) bf16 hi
__device__ __nv_bfloat16 g_Kl[BB*HH*TT*DHH];        // lo
__device__ __nv_bfloat16 g_Vth[BB*HH*DHH*TT];       // V TRANSPOSED: (bh, dh, t) hi
__device__ __nv_bfloat16 g_Vtl[BB*HH*DHH*TT];       // lo
__device__ __nv_bfloat16 g_Xh[MTOT*DD];             // x split hi (m, k)
__device__ __nv_bfloat16 g_Xl[MTOT*DD];
__device__ __nv_bfloat16 g_Wh[4*WSZ];               // Wq,Wk,Wv,Wo split hi (k, n)
__device__ __nv_bfloat16 g_Wl[4*WSZ];
__device__ __nv_bfloat16 g_Oh[MTOT*DD];             // attention out split hi (m, D)
__device__ __nv_bfloat16 g_Ol[MTOT*DD];
__device__ uint64_t g_maskbits[TT * (TT / 64)];      // bit k of word (r, w): mask[r][w*64+k]
__device__ int g_mask_mode;                          // 0=1B, 1=2B, 2=4B elements

// ---------------------------------------------------------------------------
// Helpers
// ---------------------------------------------------------------------------
__device__ __forceinline__ float bf16_round(float x) {
    return __bfloat162float(__float2bfloat16(x));
}
// returns bf16x2 with 'a' in low half (first element), 'b' in high half
__device__ __forceinline__ uint32_t pack_bf16x2(float a, float b) {
    uint32_t r;
    asm("cvt.rn.satfinite.bf16x2.f32 %0, %1, %2;" : "=r"(r) : "f"(b), "f"(a));
    return r;
}
// D += A * B  (m16n8k16, row.col, bf16 in, f32 acc)
__device__ __forceinline__ void mma16816(float* d, const uint32_t* a, uint32_t b0, uint32_t b1) {
    asm volatile("mma.sync.aligned.m16n8k16.row.col.f32.bf16.bf16.f32 "
        "{%0,%1,%2,%3}, {%4,%5,%6,%7}, {%8,%9}, {%0,%1,%2,%3};"
        : "+f"(d[0]), "+f"(d[1]), "+f"(d[2]), "+f"(d[3])
        : "r"(a[0]), "r"(a[1]), "r"(a[2]), "r"(a[3]), "r"(b0), "r"(b1));
}
__device__ __forceinline__ uint32_t smem_u32(const void* p) {
    uint32_t a;
    asm("{ .reg .u64 t; cvta.to.shared.u64 t, %1; cvt.u32.u64 %0, t; }" : "=r"(a) : "l"(p));
    return a;
}
__device__ __forceinline__ void cpa16(uint32_t d, const void* s) {
    asm volatile("cp.async.cg.shared.global [%0], [%1], 16;" :: "r"(d), "l"(s));
}
__device__ __forceinline__ void cpa_commit() {
    asm volatile("cp.async.commit_group;" ::: "memory");
}
template<int N> __device__ __forceinline__ void cpa_wait() {
    asm volatile("cp.async.wait_group %0;" :: "n"(N) : "memory");
}
__device__ __forceinline__ void ldsm4(uint32_t* d, uint32_t a) {
    asm volatile("ldmatrix.sync.aligned.m8n8.x4.shared.b16 {%0,%1,%2,%3}, [%4];"
        : "=r"(d[0]), "=r"(d[1]), "=r"(d[2]), "=r"(d[3]) : "r"(a));
}
__device__ __forceinline__ void ldsm4t(uint32_t* d, uint32_t a) {
    asm volatile("ldmatrix.sync.aligned.m8n8.x4.trans.shared.b16 {%0,%1,%2,%3}, [%4];"
        : "=r"(d[0]), "=r"(d[1]), "=r"(d[2]), "=r"(d[3]) : "r"(a));
}

// ---------------------------------------------------------------------------
// Mask dtype detection (validated)
// ---------------------------------------------------------------------------
__device__ __forceinline__ bool hw_ok(uint32_t h) {
    return h == 0u || h == 1u || h == 0x3F80u;
}
__global__ void detect_mask_kernel(const uint32_t* __restrict__ m)
{
    int lane = threadIdx.x;
    bool w4 = true, w2 = true;
    for (int i = lane; i < 1024; i += 32) {
        uint32_t w = m[i];
        if (!(w == 0u || w == 1u || w == 0x3F800000u)) w4 = false;
        if (!(hw_ok(w & 0xFFFFu) && hw_ok(w >> 16)))   w2 = false;
    }
    unsigned b4 = __ballot_sync(0xffffffffu, w4);
    unsigned b2 = __ballot_sync(0xffffffffu, w2);
    if (lane == 0)
        g_mask_mode = (b4 == 0xffffffffu) ? 2 : ((b2 == 0xffffffffu) ? 1 : 0);
}

// ---------------------------------------------------------------------------
// Mask bit-packing (validated)
// ---------------------------------------------------------------------------
__global__ void pack_mask_kernel(const void* __restrict__ mask_raw)
{
    int idx = blockIdx.x * 256 + threadIdx.x;      // 0 .. 262143
    int row = idx >> 6;
    int wi  = idx & 63;
    const int mode = g_mask_mode;
    uint64_t bits = 0;
    if (mode == 2) {
        const uint4* p = (const uint4*)((const uint32_t*)mask_raw + (size_t)row * TT + wi * 64);
#pragma unroll
        for (int w = 0; w < 16; w++) {
            uint4 v = p[w];
            uint64_t f = (uint64_t)((v.x != 0u) | ((v.y != 0u) << 1)
                                  | ((v.z != 0u) << 2) | ((v.w != 0u) << 3));
            bits |= f << (w * 4);
        }
    } else if (mode == 1) {
        const uint16_t* p = (const uint16_t*)mask_raw + (size_t)row * TT + wi * 64;
#pragma unroll
        for (int k = 0; k < 64; k++)
            bits |= (uint64_t)(p[k] != 0) << k;
    } else {
        const uint8_t* p = (const uint8_t*)mask_raw + (size_t)row * TT + wi * 64;
#pragma unroll
        for (int k = 0; k < 64; k++)
            bits |= (uint64_t)(p[k] != 0) << k;
    }
    g_maskbits[idx] = bits;
}

// ---------------------------------------------------------------------------
// Split kernels: fp32 -> bf16 hi/lo
// ---------------------------------------------------------------------------
__global__ void split_x_kernel(const float* __restrict__ x)
{
    size_t i = ((size_t)blockIdx.x * 256 + threadIdx.x) * 4;
    float4 v = *(const float4*)(x + i);
    float h0 = bf16_round(v.x), h1 = bf16_round(v.y);
    float h2 = bf16_round(v.z), h3 = bf16_round(v.w);
    *(uint2*)&g_Xh[i] = make_uint2(pack_bf16x2(h0, h1), pack_bf16x2(h2, h3));
    *(uint2*)&g_Xl[i] = make_uint2(pack_bf16x2(v.x - h0, v.y - h1), pack_bf16x2(v.z - h2, v.w - h3));
}

__global__ void split_w_kernel(const float* __restrict__ W0, const float* __restrict__ W1,
                               const float* __restrict__ W2, const float* __restrict__ W3)
{
    const float* W = (blockIdx.y == 0) ? W0 : (blockIdx.y == 1) ? W1 : (blockIdx.y == 2) ? W2 : W3;
    size_t off = (size_t)blockIdx.y * WSZ;
    size_t i = ((size_t)blockIdx.x * 256 + threadIdx.x) * 4;
    float4 v = *(const float4*)(W + i);
    float h0 = bf16_round(v.x), h1 = bf16_round(v.y);
    float h2 = bf16_round(v.z), h3 = bf16_round(v.w);
    *(uint2*)&g_Wh[off + i] = make_uint2(pack_bf16x2(h0, h1), pack_bf16x2(h2, h3));
    *(uint2*)&g_Wl[off + i] = make_uint2(pack_bf16x2(v.x - h0, v.y - h1), pack_bf16x2(v.z - h2, v.w - h3));
}

// ---------------------------------------------------------------------------
// Shared GEMM core (unchanged, validated round 9)
// ---------------------------------------------------------------------------
#define SMA_SZ (2*2*128*40)
#define SMB_SZ (2*2*32*72)
#define GEMM_SMEM ((SMA_SZ + SMB_SZ) * 2)   // bytes = 59392

__device__ __forceinline__ void gemm_core(
    const __nv_bfloat16* __restrict__ Ah, const __nv_bfloat16* __restrict__ Al,
    const __nv_bfloat16* __restrict__ Bh, const __nv_bfloat16* __restrict__ Bl,
    int m0, int n0, float c[2][4][4])
{
    extern __shared__ __nv_bfloat16 sm[];
    const int tid = threadIdx.x;
    const int wid = tid >> 5, lane = tid & 31;
    const int wr = wid >> 1, wc = wid & 1;
    const int quad = lane >> 3, r8 = lane & 7;

#pragma unroll
    for (int mt = 0; mt < 2; mt++)
#pragma unroll
        for (int nt = 0; nt < 4; nt++)
#pragma unroll
            for (int e = 0; e < 4; e++) c[mt][nt][e] = 0.f;

    auto preload = [&](int buf, int k0) {
#pragma unroll
        for (int i = 0; i < 6; i++) {
            int ch = tid + i * 256;            // 0..1535
            if (ch < 1024) {                   // A: 2 x 128 rows x 4 chunks
                int h = ch >> 9, rem = ch & 511;
                int row = rem >> 2, kc = rem & 3;
                uint32_t dst = smem_u32(&sm[((buf * 2 + h) * 128 + row) * 40 + kc * 8]);
                cpa16(dst, (h ? Al : Ah) + (size_t)(m0 + row) * DD + k0 + kc * 8);
            } else {                           // B: 2 x 32 rows x 8 chunks
                int d2 = ch - 1024;
                int h = d2 >> 8, rem = d2 & 255;
                int row = rem >> 3, nc = rem & 7;
                uint32_t dst = smem_u32(&sm[SMA_SZ + ((buf * 2 + h) * 32 + row) * 72 + nc * 8]);
                cpa16(dst, (h ? Bl : Bh) + (size_t)(k0 + row) * DD + n0 + nc * 8);
            }
        }
        cpa_commit();
    };

    preload(0, 0);
    for (int s = 0; s < 16; s++) {
        if (s + 1 < 16) { preload((s + 1) & 1, (s + 1) * 32); cpa_wait<1>(); }
        else            { cpa_wait<0>(); }
        __syncthreads();
        const int buf = s & 1;

#pragma unroll
        for (int chunk = 0; chunk < 2; chunk++) {
            uint32_t ah0[4], al0[4], ah1[4], al1[4];
            int arow0 = wr * 32 + (quad & 1) * 8 + r8;
            int acol  = chunk * 16 + (quad >> 1) * 8;
            ldsm4(ah0, smem_u32(&sm[((buf * 2 + 0) * 128 + arow0) * 40 + acol]));
            ldsm4(al0, smem_u32(&sm[((buf * 2 + 1) * 128 + arow0) * 40 + acol]));
            ldsm4(ah1, smem_u32(&sm[((buf * 2 + 0) * 128 + arow0 + 16) * 40 + acol]));
            ldsm4(al1, smem_u32(&sm[((buf * 2 + 1) * 128 + arow0 + 16) * 40 + acol]));
#pragma unroll
            for (int ntp = 0; ntp < 2; ntp++) {
                uint32_t bhf[4], blf[4];
                int brow = chunk * 16 + (quad & 1) * 8 + r8;
                int bcol = wc * 32 + ntp * 16 + (quad >> 1) * 8;
                ldsm4t(bhf, smem_u32(&sm[SMA_SZ + ((buf * 2 + 0) * 32 + brow) * 72 + bcol]));
                ldsm4t(blf, smem_u32(&sm[SMA_SZ + ((buf * 2 + 1) * 32 + brow) * 72 + bcol]));
#pragma unroll
                for (int half = 0; half < 2; half++) {
                    int nt = ntp * 2 + half;
                    uint32_t b0 = bhf[half * 2], b1 = bhf[half * 2 + 1];
                    uint32_t bl0 = blf[half * 2], bl1 = blf[half * 2 + 1];
                    mma16816(c[0][nt], ah0, b0, b1);
                    mma16816(c[0][nt], al0, b0, b1);
                    mma16816(c[0][nt], ah0, bl0, bl1);
                    mma16816(c[1][nt], ah1, b0, b1);
                    mma16816(c[1][nt], al1, b0, b1);
                    mma16816(c[1][nt], ah1, bl0, bl1);
                }
            }
        }
        __syncthreads();
    }
}

// ---------------------------------------------------------------------------
// QKV projection via HMMA (unchanged, validated round 9)
// ---------------------------------------------------------------------------
__global__ void __launch_bounds__(256, 2)
gemm_qkv_mma(const float* __restrict__ bq, const float* __restrict__ bk,
             const float* __restrict__ bv)
{
    const int mode = blockIdx.z;
    const int m0 = blockIdx.y * 128, n0 = blockIdx.x * 64;
    const float* bias = (mode == 0) ? bq : (mode == 1) ? bk : bv;

    float c[2][4][4];
    gemm_core(g_Xh, g_Xl, g_Wh + (size_t)mode * WSZ, g_Wl + (size_t)mode * WSZ, m0, n0, c);

    const int tid = threadIdx.x, wid = tid >> 5, lane = tid & 31;
    const int wr = wid >> 1, wc = wid & 1, g = lane >> 2, tg = lane & 3;

#pragma unroll
    for (int mt = 0; mt < 2; mt++) {
#pragma unroll
        for (int nt = 0; nt < 4; nt++) {
            int n = n0 + wc * 32 + nt * 8 + tg * 2;
            int h = n >> 6, dh = n & 63;
            float b0v = bias[n], b1v = bias[n + 1];
#pragma unroll
            for (int e = 0; e < 2; e++) {
                int m = m0 + wr * 32 + mt * 16 + g + e * 8;
                int b = m >> 12, t = m & 4095;
                float v0 = c[mt][nt][e * 2 + 0] + b0v;
                float v1 = c[mt][nt][e * 2 + 1] + b1v;
                size_t bhh = (size_t)b * HH + h;
                if (mode == 0) {
                    *(float2*)&g_Q[(bhh * TT + t) * DHH + dh] = make_float2(v0, v1);
                } else if (mode == 1) {
                    float h0 = bf16_round(v0), h1 = bf16_round(v1);
                    size_t idx = (bhh * TT + t) * DHH + dh;
                    *(uint32_t*)&g_Kh[idx] = pack_bf16x2(h0, h1);
                    *(uint32_t*)&g_Kl[idx] = pack_bf16x2(v0 - h0, v1 - h1);
                } else {
                    float h0 = bf16_round(v0), h1 = bf16_round(v1);
                    size_t i0 = (bhh * DHH + dh) * TT + t;
                    size_t i1 = (bhh * DHH + dh + 1) * TT + t;
                    g_Vth[i0] = __float2bfloat16(h0);
                    g_Vtl[i0] = __float2bfloat16(v0 - h0);
                    g_Vth[i1] = __float2bfloat16(h1);
                    g_Vtl[i1] = __float2bfloat16(v1 - h1);
                }
            }
        }
    }
}

// ---------------------------------------------------------------------------
// Output projection via HMMA (unchanged, validated round 9)
// ---------------------------------------------------------------------------
__global__ void __launch_bounds__(256, 2)
gemm_out_mma(const float* __restrict__ bo, float* __restrict__ out)
{
    const int m0 = blockIdx.y * 128, n0 = blockIdx.x * 64;
    float c[2][4][4];
    gemm_core(g_Oh, g_Ol, g_Wh + 3 * (size_t)WSZ, g_Wl + 3 * (size_t)WSZ, m0, n0, c);

    const int tid = threadIdx.x, wid = tid >> 5, lane = tid & 31;
    const int wr = wid >> 1, wc = wid & 1, g = lane >> 2, tg = lane & 3;

#pragma unroll
    for (int mt = 0; mt < 2; mt++) {
#pragma unroll
        for (int nt = 0; nt < 4; nt++) {
            int n = n0 + wc * 32 + nt * 8 + tg * 2;
            float b0v = bo[n], b1v = bo[n + 1];
#pragma unroll
            for (int e = 0; e < 2; e++) {
                int m = m0 + wr * 32 + mt * 16 + g + e * 8;
                float v0 = c[mt][nt][e * 2 + 0] + b0v;
                float v1 = c[mt][nt][e * 2 + 1] + b1v;
                *(float2*)&out[(size_t)m * DD + n] = make_float2(v0, v1);
            }
        }
    }
}

// ---------------------------------------------------------------------------
// Kernel 2: flash attention (round-8 structure: 4 warps, BM=64, 2 CTAs/SM),
// with the ONLY change being ldmatrix.x4 fragment loads in place of scalar
// LDS (lane->fragment mapping validated in round 10).
// ---------------------------------------------------------------------------
#define SROW 72   // smem row stride (bf16 units)

__global__ void __launch_bounds__(128, 2)
flash_attn_mma(int dummy)
{
    __shared__ __nv_bfloat16 sKh[64 * SROW];
    __shared__ __nv_bfloat16 sKl[64 * SROW];
    __shared__ __nv_bfloat16 sVh[64 * SROW];   // [dh][key]
    __shared__ __nv_bfloat16 sVl[64 * SROW];

    const int tid  = threadIdx.x;
    const int wid  = tid >> 5;
    const int lane = tid & 31;
    const int g    = lane >> 2;      // group row 0..7
    const int tg   = lane & 3;       // thread-in-group 0..3
    const int bh   = blockIdx.x;     // 0..15
    const int q0   = blockIdx.y * 64;
    const int r0   = q0 + wid * 16;  // this warp's first q row

    const __nv_bfloat16* gKh = g_Kh + (size_t)bh * TT * DHH;
    const __nv_bfloat16* gKl = g_Kl + (size_t)bh * TT * DHH;
    const __nv_bfloat16* gVh = g_Vth + (size_t)bh * DHH * TT;
    const __nv_bfloat16* gVl = g_Vtl + (size_t)bh * DHH * TT;

    // ldmatrix lane addressing (validated round 10):
    // lanes 0-7: rows 0-7 @k+0 | 8-15: rows 0-7 @k+8 | 16-23: rows 8-15 @k+0
    // | 24-31: rows 8-15 @k+8  -> d0=b0(n0..7) d1=b1(n0..7) d2=b0(n8..15) d3=b1(n8..15)
    const int rowsel = (lane & 7) + ((lane >> 4) << 3);
    const int kadd   = ((lane >> 3) & 1) * 8;
    const uint32_t lane_off = (uint32_t)(rowsel * SROW + kadd) * 2;   // bytes
    const uint32_t aKh = smem_u32(sKh) + lane_off;
    const uint32_t aKl = smem_u32(sKl) + lane_off;
    const uint32_t aVh = smem_u32(sVh) + lane_off;
    const uint32_t aVl = smem_u32(sVl) + lane_off;

    // ---- load Q A-fragments (hi/lo), scaled by 1/8 ----
    uint32_t qh[4][4], ql[4][4];
    {
        const float* q0p = g_Q + ((size_t)bh * TT + r0 + g) * DHH;
        const float* q8p = q0p + 8 * DHH;
#pragma unroll
        for (int ks = 0; ks < 4; ks++) {
            int c0 = ks * 16 + tg * 2;
            int c1 = c0 + 8;
            float2 v00 = *(const float2*)(q0p + c0);
            float2 v10 = *(const float2*)(q8p + c0);
            float2 v01 = *(const float2*)(q0p + c1);
            float2 v11 = *(const float2*)(q8p + c1);
            float a, b, ah, bh_;
            a = v00.x * 0.125f; b = v00.y * 0.125f; ah = bf16_round(a); bh_ = bf16_round(b);
            qh[ks][0] = pack_bf16x2(ah, bh_); ql[ks][0] = pack_bf16x2(a - ah, b - bh_);
            a = v10.x * 0.125f; b = v10.y * 0.125f; ah = bf16_round(a); bh_ = bf16_round(b);
            qh[ks][1] = pack_bf16x2(ah, bh_); ql[ks][1] = pack_bf16x2(a - ah, b - bh_);
            a = v01.x * 0.125f; b = v01.y * 0.125f; ah = bf16_round(a); bh_ = bf16_round(b);
            qh[ks][2] = pack_bf16x2(ah, bh_); ql[ks][2] = pack_bf16x2(a - ah, b - bh_);
            a = v11.x * 0.125f; b = v11.y * 0.125f; ah = bf16_round(a); bh_ = bf16_round(b);
            qh[ks][3] = pack_bf16x2(ah, bh_); ql[ks][3] = pack_bf16x2(a - ah, b - bh_);
        }
    }

    const uint64_t* mrow0 = g_maskbits + (size_t)(r0 + g) * 64;
    const uint64_t* mrow8 = mrow0 + 8 * 64;

    float o[8][4];
#pragma unroll
    for (int nt = 0; nt < 8; nt++)
#pragma unroll
        for (int i = 0; i < 4; i++) o[nt][i] = 0.f;
    float l0 = 0.f, l1 = 0.f;

    for (int kt = 0; kt < TT / 64; kt++) {
        const int k0 = kt * 64;
        __syncthreads();   // previous tile's fragment reads done before overwrite

        // ---- stage K hi/lo and V^T hi/lo (row-major, pad SROW) ----
#pragma unroll
        for (int it = 0; it < 4; it++) {
            int slot = tid + it * 128;        // 0..511
            int r = slot >> 3, j = slot & 7;  // row, 16B chunk
            *(uint4*)&sKh[r * SROW + j * 8] = *(const uint4*)(gKh + (size_t)(k0 + r) * DHH + j * 8);
            *(uint4*)&sKl[r * SROW + j * 8] = *(const uint4*)(gKl + (size_t)(k0 + r) * DHH + j * 8);
            *(uint4*)&sVh[r * SROW + j * 8] = *(const uint4*)(gVh + (size_t)r * TT + k0 + j * 8);
            *(uint4*)&sVl[r * SROW + j * 8] = *(const uint4*)(gVl + (size_t)r * TT + k0 + j * 8);
        }
        __syncthreads();

        // ---- S = Q K^T  (hi*hi + lo*hi + hi*lo) via ldmatrix ----
        float s[8][4];
#pragma unroll
        for (int nt = 0; nt < 8; nt++)
#pragma unroll
            for (int i = 0; i < 4; i++) s[nt][i] = 0.f;

#pragma unroll
        for (int p = 0; p < 4; p++) {           // 16 n-rows per group
#pragma unroll
            for (int ks = 0; ks < 4; ks++) {    // 16 k per chunk
                uint32_t off = (uint32_t)(p * 16 * SROW + ks * 16) * 2;
                uint32_t kh[4], kl[4];
                ldsm4(kh, aKh + off);
                ldsm4(kl, aKl + off);
                mma16816(s[2 * p],     qh[ks], kh[0], kh[1]);
                mma16816(s[2 * p],     ql[ks], kh[0], kh[1]);
                mma16816(s[2 * p],     qh[ks], kl[0], kl[1]);
                mma16816(s[2 * p + 1], qh[ks], kh[2], kh[3]);
                mma16816(s[2 * p + 1], ql[ks], kh[2], kh[3]);
                mma16816(s[2 * p + 1], qh[ks], kl[2], kl[3]);
            }
        }

        // ---- mask + exp + repack P as A-fragments (hi/lo) ----
        const uint64_t m0 = mrow0[kt];
        const uint64_t m8 = mrow8[kt];
        uint32_t pah[4][4], pal[4][4];
#pragma unroll
        for (int nt = 0; nt < 8; nt++) {
            int cb = nt * 8 + tg * 2;
            float p0 = ((m0 >> cb) & 1ull)       ? __expf(s[nt][0]) : 0.f;
            float p1 = ((m0 >> (cb + 1)) & 1ull) ? __expf(s[nt][1]) : 0.f;
            float p2 = ((m8 >> cb) & 1ull)       ? __expf(s[nt][2]) : 0.f;
            float p3 = ((m8 >> (cb + 1)) & 1ull) ? __expf(s[nt][3]) : 0.f;
            l0 += p0 + p1;
            l1 += p2 + p3;
            float h0 = bf16_round(p0), h1 = bf16_round(p1);
            float h2 = bf16_round(p2), h3 = bf16_round(p3);
            int ks = nt >> 1;
            int hi = (nt & 1) ? 2 : 0;
            pah[ks][hi]     = pack_bf16x2(h0, h1);
            pah[ks][hi + 1] = pack_bf16x2(h2, h3);
            pal[ks][hi]     = pack_bf16x2(p0 - h0, p1 - h1);
            pal[ks][hi + 1] = pack_bf16x2(p2 - h2, p3 - h3);
        }

        // ---- O += P V  (hi*hi + lo*hi + hi*lo) via ldmatrix ----
#pragma unroll
        for (int p = 0; p < 4; p++) {
#pragma unroll
            for (int ks = 0; ks < 4; ks++) {
                uint32_t off = (uint32_t)(p * 16 * SROW + ks * 16) * 2;
                uint32_t vh[4], vl[4];
                ldsm4(vh, aVh + off);
                ldsm4(vl, aVl + off);
                mma16816(o[2 * p],     pah[ks], vh[0], vh[1]);
                mma16816(o[2 * p],     pal[ks], vh[0], vh[1]);
                mma16816(o[2 * p],     pah[ks], vl[0], vl[1]);
                mma16816(o[2 * p + 1], pah[ks], vh[2], vh[3]);
                mma16816(o[2 * p + 1], pal[ks], vh[2], vh[3]);
                mma16816(o[2 * p + 1], pah[ks], vl[2], vl[3]);
            }
        }
    }

    // ---- epilogue: reduce l, normalize, split, store packed (b,t,D) ----
    l0 += __shfl_xor_sync(0xffffffffu, l0, 1);
    l0 += __shfl_xor_sync(0xffffffffu, l0, 2);
    l1 += __shfl_xor_sync(0xffffffffu, l1, 1);
    l1 += __shfl_xor_sync(0xffffffffu, l1, 2);
    float inv0 = 1.f / l0, inv1 = 1.f / l1;

    const int b = bh >> 3, h = bh & 7;
    size_t base0 = ((size_t)b * TT + (r0 + g)) * DD + h * DHH;
    size_t base8 = base0 + (size_t)8 * DD;
#pragma unroll
    for (int nt = 0; nt < 8; nt++) {
        int c = nt * 8 + tg * 2;
        float v0 = o[nt][0] * inv0, v1 = o[nt][1] * inv0;
        float v2 = o[nt][2] * inv1, v3 = o[nt][3] * inv1;
        float h0 = bf16_round(v0), h1 = bf16_round(v1);
        float h2 = bf16_round(v2), h3 = bf16_round(v3);
        *(uint32_t*)&g_Oh[base0 + c] = pack_bf16x2(h0, h1);
        *(uint32_t*)&g_Ol[base0 + c] = pack_bf16x2(v0 - h0, v1 - h1);
        *(uint32_t*)&g_Oh[base8 + c] = pack_bf16x2(h2, h3);
        *(uint32_t*)&g_Ol[base8 + c] = pack_bf16x2(v2 - h2, v3 - h3);
    }
}

// ---------------------------------------------------------------------------
// Launch.  Inputs identified BY SIZE.
// ---------------------------------------------------------------------------
extern "C" void kernel_launch(void* const* d_in, const int* in_sizes, int n_in,
                              void* d_out, int out_size)
{
    const float* x = nullptr;
    const float* Ws[4] = {nullptr, nullptr, nullptr, nullptr};
    const float* bs[4] = {nullptr, nullptr, nullptr, nullptr};
    const void*  mask = nullptr;
    int wc = 0, bc = 0;
    for (int i = 0; i < n_in; i++) {
        int sz = in_sizes[i];
        if (sz == TT * TT)            mask = d_in[i];
        else if (sz == MTOT * DD)     x = (const float*)d_in[i];
        else if (sz == DD * DD)       { if (wc < 4) Ws[wc++] = (const float*)d_in[i]; }
        else if (sz == DD)            { if (bc < 4) bs[bc++] = (const float*)d_in[i]; }
    }
    float* out = (float*)d_out;

    cudaFuncSetAttribute(gemm_qkv_mma, cudaFuncAttributeMaxDynamicSharedMemorySize, GEMM_SMEM);
    cudaFuncSetAttribute(gemm_out_mma, cudaFuncAttributeMaxDynamicSharedMemorySize, GEMM_SMEM);

    detect_mask_kernel<<<1, 32>>>((const uint32_t*)mask);
    pack_mask_kernel<<<1024, 256>>>(mask);
    split_x_kernel<<<MTOT * DD / 1024, 256>>>(x);
    split_w_kernel<<<dim3(WSZ / 1024, 4), 256>>>(Ws[0], Ws[1], Ws[2], Ws[3]);
    gemm_qkv_mma<<<dim3(DD / 64, MTOT / 128, 3), 256, GEMM_SMEM>>>(bs[0], bs[1], bs[2]);
    flash_attn_mma<<<dim3(BB * HH, TT / 64), 128>>>(0);
    gemm_out_mma<<<dim3(DD / 64, MTOT / 128), 256, GEMM_SMEM>>>(bs[3], out);
}

// round 14
// speedup vs baseline: 1.3154x; 1.3154x over previous
#include <cuda_runtime.h>
#include <cuda_bf16.h>
#include <cuda_fp16.h>
#include <cstdint>

// Problem constants
#define BB   2
#define TT   4096
#define DD   512
#define HH   8
#define DHH  64
#define MTOT (BB*TT)          // 8192
#define WSZ  (DD*DD)

// Scratch (allocation-free __device__ globals)
__device__ float g_Q[BB*HH*TT*DHH];                 // (bh, t, dh) fp32
__device__ __half g_Kh[BB*HH*TT*DHH];               // (bh, t, dh) fp16 (single)
__device__ __half g_Vth[BB*HH*DHH*TT];              // V TRANSPOSED: (bh, dh, t) fp16 hi
__device__ __half g_Vtl[BB*HH*DHH*TT];              // lo
__device__ __nv_bfloat16 g_Xh[MTOT*DD];             // x split hi (m, k)  [projections]
__device__ __nv_bfloat16 g_Xl[MTOT*DD];
__device__ __nv_bfloat16 g_Wh[4*WSZ];               // Wq,Wk,Wv,Wo split hi (k, n)
__device__ __nv_bfloat16 g_Wl[4*WSZ];
__device__ __nv_bfloat16 g_Oh[MTOT*DD];             // attention out split hi (m, D)
__device__ __nv_bfloat16 g_Ol[MTOT*DD];
__device__ uint64_t g_maskbits[TT * (TT / 64)];      // bit k of word (r, w): mask[r][w*64+k]

// ---------------------------------------------------------------------------
// Helpers
// ---------------------------------------------------------------------------
__device__ __forceinline__ float bf16_round(float x) {
    return __bfloat162float(__float2bfloat16(x));
}
__device__ __forceinline__ uint32_t pack_bf16x2(float a, float b) {   // a -> low half
    uint32_t r;
    asm("cvt.rn.satfinite.bf16x2.f32 %0, %1, %2;" : "=r"(r) : "f"(b), "f"(a));
    return r;
}
__device__ __forceinline__ uint32_t pack_f16x2(float a, float b) {    // a -> low half
    uint32_t r;
    asm("cvt.rn.f16x2.f32 %0, %1, %2;" : "=r"(r) : "f"(b), "f"(a));
    return r;
}
// D += A * B  (m16n8k16, row.col, bf16 in, f32 acc)
__device__ __forceinline__ void mma16816(float* d, const uint32_t* a, uint32_t b0, uint32_t b1) {
    asm volatile("mma.sync.aligned.m16n8k16.row.col.f32.bf16.bf16.f32 "
        "{%0,%1,%2,%3}, {%4,%5,%6,%7}, {%8,%9}, {%0,%1,%2,%3};"
        : "+f"(d[0]), "+f"(d[1]), "+f"(d[2]), "+f"(d[3])
        : "r"(a[0]), "r"(a[1]), "r"(a[2]), "r"(a[3]), "r"(b0), "r"(b1));
}
// D += A * B  (m16n8k16, row.col, fp16 in, f32 acc)
__device__ __forceinline__ void mma16816h(float* d, const uint32_t* a, uint32_t b0, uint32_t b1) {
    asm volatile("mma.sync.aligned.m16n8k16.row.col.f32.f16.f16.f32 "
        "{%0,%1,%2,%3}, {%4,%5,%6,%7}, {%8,%9}, {%0,%1,%2,%3};"
        : "+f"(d[0]), "+f"(d[1]), "+f"(d[2]), "+f"(d[3])
        : "r"(a[0]), "r"(a[1]), "r"(a[2]), "r"(a[3]), "r"(b0), "r"(b1));
}
__device__ __forceinline__ uint32_t smem_u32(const void* p) {
    uint32_t a;
    asm("{ .reg .u64 t; cvta.to.shared.u64 t, %1; cvt.u32.u64 %0, t; }" : "=r"(a) : "l"(p));
    return a;
}
__device__ __forceinline__ void cpa16(uint32_t d, const void* s) {
    asm volatile("cp.async.cg.shared.global [%0], [%1], 16;" :: "r"(d), "l"(s));
}
__device__ __forceinline__ void cpa_commit() {
    asm volatile("cp.async.commit_group;" ::: "memory");
}
template<int N> __device__ __forceinline__ void cpa_wait() {
    asm volatile("cp.async.wait_group %0;" :: "n"(N) : "memory");
}
__device__ __forceinline__ void ldsm4(uint32_t* d, uint32_t a) {
    asm volatile("ldmatrix.sync.aligned.m8n8.x4.shared.b16 {%0,%1,%2,%3}, [%4];"
        : "=r"(d[0]), "=r"(d[1]), "=r"(d[2]), "=r"(d[3]) : "r"(a));
}
__device__ __forceinline__ void ldsm4t(uint32_t* d, uint32_t a) {
    asm volatile("ldmatrix.sync.aligned.m8n8.x4.trans.shared.b16 {%0,%1,%2,%3}, [%4];"
        : "=r"(d[0]), "=r"(d[1]), "=r"(d[2]), "=r"(d[3]) : "r"(a));
}

// ---------------------------------------------------------------------------
// Mask pack with inline dtype detection (each block redundantly classifies
// the first 4KB; __syncthreads_and reduces).  Launch #1.
// ---------------------------------------------------------------------------
__device__ __forceinline__ bool hw_ok(uint32_t h) {
    return h == 0u || h == 1u || h == 0x3F80u;
}
__global__ void pack_mask_kernel(const void* __restrict__ mask_raw)
{
    const uint32_t* m = (const uint32_t*)mask_raw;
    const int tid = threadIdx.x;
    bool w4 = true, w2 = true;
    for (int i = tid; i < 1024; i += 256) {
        uint32_t w = m[i];
        if (!(w == 0u || w == 1u || w == 0x3F800000u)) w4 = false;
        if (!(hw_ok(w & 0xFFFFu) && hw_ok(w >> 16)))   w2 = false;
    }
    int all4 = __syncthreads_and(w4 ? 1 : 0);
    int all2 = __syncthreads_and(w2 ? 1 : 0);
    const int mode = all4 ? 2 : (all2 ? 1 : 0);

    int idx = blockIdx.x * 256 + tid;      // 0 .. 262143
    int row = idx >> 6;
    int wi  = idx & 63;
    uint64_t bits = 0;
    if (mode == 2) {
        const uint4* p = (const uint4*)((const uint32_t*)mask_raw + (size_t)row * TT + wi * 64);
#pragma unroll
        for (int w = 0; w < 16; w++) {
            uint4 v = p[w];
            uint64_t f = (uint64_t)((v.x != 0u) | ((v.y != 0u) << 1)
                                  | ((v.z != 0u) << 2) | ((v.w != 0u) << 3));
            bits |= f << (w * 4);
        }
    } else if (mode == 1) {
        const uint16_t* p = (const uint16_t*)mask_raw + (size_t)row * TT + wi * 64;
#pragma unroll
        for (int k = 0; k < 64; k++)
            bits |= (uint64_t)(p[k] != 0) << k;
    } else {
        const uint8_t* p = (const uint8_t*)mask_raw + (size_t)row * TT + wi * 64;
#pragma unroll
        for (int k = 0; k < 64; k++)
            bits |= (uint64_t)(p[k] != 0) << k;
    }
    g_maskbits[idx] = bits;
}

// ---------------------------------------------------------------------------
// Merged split: x then the 4 weights, fp32 -> bf16 hi/lo.  Launch #2.
// Grid: (MTOT*DD + 4*WSZ) / 1024 = 5120 blocks x 256 threads, 4 elems/thread.
// ---------------------------------------------------------------------------
__global__ void split_all_kernel(const float* __restrict__ x,
                                 const float* __restrict__ W0, const float* __restrict__ W1,
                                 const float* __restrict__ W2, const float* __restrict__ W3)
{
    size_t gid = ((size_t)blockIdx.x * 256 + threadIdx.x) * 4;
    const float* src;
    __nv_bfloat16 *dsth, *dstl;
    if (gid < (size_t)MTOT * DD) {
        src = x + gid; dsth = g_Xh + gid; dstl = g_Xl + gid;
    } else {
        size_t w = gid - (size_t)MTOT * DD;
        int wi = (int)(w / WSZ);
        size_t wo = w % WSZ;
        const float* W = (wi == 0) ? W0 : (wi == 1) ? W1 : (wi == 2) ? W2 : W3;
        src = W + wo; dsth = g_Wh + w; dstl = g_Wl + w;
    }
    float4 v = *(const float4*)src;
    float h0 = bf16_round(v.x), h1 = bf16_round(v.y);
    float h2 = bf16_round(v.z), h3 = bf16_round(v.w);
    *(uint2*)dsth = make_uint2(pack_bf16x2(h0, h1), pack_bf16x2(h2, h3));
    *(uint2*)dstl = make_uint2(pack_bf16x2(v.x - h0, v.y - h1), pack_bf16x2(v.z - h2, v.w - h3));
}

// ---------------------------------------------------------------------------
// Shared GEMM core (unchanged, validated round 9)
// ---------------------------------------------------------------------------
#define SMA_SZ (2*2*128*40)
#define SMB_SZ (2*2*32*72)
#define GEMM_SMEM ((SMA_SZ + SMB_SZ) * 2)   // bytes = 59392

__device__ __forceinline__ void gemm_core(
    const __nv_bfloat16* __restrict__ Ah, const __nv_bfloat16* __restrict__ Al,
    const __nv_bfloat16* __restrict__ Bh, const __nv_bfloat16* __restrict__ Bl,
    int m0, int n0, float c[2][4][4])
{
    extern __shared__ __nv_bfloat16 sm[];
    const int tid = threadIdx.x;
    const int wid = tid >> 5, lane = tid & 31;
    const int wr = wid >> 1, wc = wid & 1;
    const int quad = lane >> 3, r8 = lane & 7;

#pragma unroll
    for (int mt = 0; mt < 2; mt++)
#pragma unroll
        for (int nt = 0; nt < 4; nt++)
#pragma unroll
            for (int e = 0; e < 4; e++) c[mt][nt][e] = 0.f;

    auto preload = [&](int buf, int k0) {
#pragma unroll
        for (int i = 0; i < 6; i++) {
            int ch = tid + i * 256;            // 0..1535
            if (ch < 1024) {                   // A: 2 x 128 rows x 4 chunks
                int h = ch >> 9, rem = ch & 511;
                int row = rem >> 2, kc = rem & 3;
                uint32_t dst = smem_u32(&sm[((buf * 2 + h) * 128 + row) * 40 + kc * 8]);
                cpa16(dst, (h ? Al : Ah) + (size_t)(m0 + row) * DD + k0 + kc * 8);
            } else {                           // B: 2 x 32 rows x 8 chunks
                int d2 = ch - 1024;
                int h = d2 >> 8, rem = d2 & 255;
                int row = rem >> 3, nc = rem & 7;
                uint32_t dst = smem_u32(&sm[SMA_SZ + ((buf * 2 + h) * 32 + row) * 72 + nc * 8]);
                cpa16(dst, (h ? Bl : Bh) + (size_t)(k0 + row) * DD + n0 + nc * 8);
            }
        }
        cpa_commit();
    };

    preload(0, 0);
    for (int s = 0; s < 16; s++) {
        if (s + 1 < 16) { preload((s + 1) & 1, (s + 1) * 32); cpa_wait<1>(); }
        else            { cpa_wait<0>(); }
        __syncthreads();
        const int buf = s & 1;

#pragma unroll
        for (int chunk = 0; chunk < 2; chunk++) {
            uint32_t ah0[4], al0[4], ah1[4], al1[4];
            int arow0 = wr * 32 + (quad & 1) * 8 + r8;
            int acol  = chunk * 16 + (quad >> 1) * 8;
            ldsm4(ah0, smem_u32(&sm[((buf * 2 + 0) * 128 + arow0) * 40 + acol]));
            ldsm4(al0, smem_u32(&sm[((buf * 2 + 1) * 128 + arow0) * 40 + acol]));
            ldsm4(ah1, smem_u32(&sm[((buf * 2 + 0) * 128 + arow0 + 16) * 40 + acol]));
            ldsm4(al1, smem_u32(&sm[((buf * 2 + 1) * 128 + arow0 + 16) * 40 + acol]));
#pragma unroll
            for (int ntp = 0; ntp < 2; ntp++) {
                uint32_t bhf[4], blf[4];
                int brow = chunk * 16 + (quad & 1) * 8 + r8;
                int bcol = wc * 32 + ntp * 16 + (quad >> 1) * 8;
                ldsm4t(bhf, smem_u32(&sm[SMA_SZ + ((buf * 2 + 0) * 32 + brow) * 72 + bcol]));
                ldsm4t(blf, smem_u32(&sm[SMA_SZ + ((buf * 2 + 1) * 32 + brow) * 72 + bcol]));
#pragma unroll
                for (int half = 0; half < 2; half++) {
                    int nt = ntp * 2 + half;
                    uint32_t b0 = bhf[half * 2], b1 = bhf[half * 2 + 1];
                    uint32_t bl0 = blf[half * 2], bl1 = blf[half * 2 + 1];
                    mma16816(c[0][nt], ah0, b0, b1);
                    mma16816(c[0][nt], al0, b0, b1);
                    mma16816(c[0][nt], ah0, bl0, bl1);
                    mma16816(c[1][nt], ah1, b0, b1);
                    mma16816(c[1][nt], al1, b0, b1);
                    mma16816(c[1][nt], ah1, bl0, bl1);
                }
            }
        }
        __syncthreads();
    }
}

// ---------------------------------------------------------------------------
// QKV projection via HMMA.  Epilogue: Q fp32; K fp16 single; V fp16 hi/lo (T).
// ---------------------------------------------------------------------------
__global__ void __launch_bounds__(256, 2)
gemm_qkv_mma(const float* __restrict__ bq, const float* __restrict__ bk,
             const float* __restrict__ bv)
{
    const int mode = blockIdx.z;
    const int m0 = blockIdx.y * 128, n0 = blockIdx.x * 64;
    const float* bias = (mode == 0) ? bq : (mode == 1) ? bk : bv;

    float c[2][4][4];
    gemm_core(g_Xh, g_Xl, g_Wh + (size_t)mode * WSZ, g_Wl + (size_t)mode * WSZ, m0, n0, c);

    const int tid = threadIdx.x, wid = tid >> 5, lane = tid & 31;
    const int wr = wid >> 1, wc = wid & 1, g = lane >> 2, tg = lane & 3;

#pragma unroll
    for (int mt = 0; mt < 2; mt++) {
#pragma unroll
        for (int nt = 0; nt < 4; nt++) {
            int n = n0 + wc * 32 + nt * 8 + tg * 2;
            int h = n >> 6, dh = n & 63;
            float b0v = bias[n], b1v = bias[n + 1];
#pragma unroll
            for (int e = 0; e < 2; e++) {
                int m = m0 + wr * 32 + mt * 16 + g + e * 8;
                int b = m >> 12, t = m & 4095;
                float v0 = c[mt][nt][e * 2 + 0] + b0v;
                float v1 = c[mt][nt][e * 2 + 1] + b1v;
                size_t bhh = (size_t)b * HH + h;
                if (mode == 0) {
                    *(float2*)&g_Q[(bhh * TT + t) * DHH + dh] = make_float2(v0, v1);
                } else if (mode == 1) {
                    size_t idx = (bhh * TT + t) * DHH + dh;
                    *(uint32_t*)&g_Kh[idx] = pack_f16x2(v0, v1);
                } else {
                    __half h0 = __float2half_rn(v0);
                    __half h1 = __float2half_rn(v1);
                    size_t i0 = (bhh * DHH + dh) * TT + t;
                    size_t i1 = (bhh * DHH + dh + 1) * TT + t;
                    g_Vth[i0] = h0;
                    g_Vtl[i0] = __float2half_rn(v0 - __half2float(h0));
                    g_Vth[i1] = h1;
                    g_Vtl[i1] = __float2half_rn(v1 - __half2float(h1));
                }
            }
        }
    }
}

// ---------------------------------------------------------------------------
// Output projection via HMMA (unchanged, validated round 9)
// ---------------------------------------------------------------------------
__global__ void __launch_bounds__(256, 2)
gemm_out_mma(const float* __restrict__ bo, float* __restrict__ out)
{
    const int m0 = blockIdx.y * 128, n0 = blockIdx.x * 64;
    float c[2][4][4];
    gemm_core(g_Oh, g_Ol, g_Wh + 3 * (size_t)WSZ, g_Wl + 3 * (size_t)WSZ, m0, n0, c);

    const int tid = threadIdx.x, wid = tid >> 5, lane = tid & 31;
    const int wr = wid >> 1, wc = wid & 1, g = lane >> 2, tg = lane & 3;

#pragma unroll
    for (int mt = 0; mt < 2; mt++) {
#pragma unroll
        for (int nt = 0; nt < 4; nt++) {
            int n = n0 + wc * 32 + nt * 8 + tg * 2;
            float b0v = bo[n], b1v = bo[n + 1];
#pragma unroll
            for (int e = 0; e < 2; e++) {
                int m = m0 + wr * 32 + mt * 16 + g + e * 8;
                float v0 = c[mt][nt][e * 2 + 0] + b0v;
                float v1 = c[mt][nt][e * 2 + 1] + b1v;
                *(float2*)&out[(size_t)m * DD + n] = make_float2(v0, v1);
            }
        }
    }
}

// ---------------------------------------------------------------------------
// Kernel: flash attention.  Round-8/9 structure EXACTLY (4 warps, BM=64,
// scalar LDS fragment loads, 2 CTAs/SM).  fp16 numerics:
//   S = Qh*Kh (1 MMA), O += Ph*Vh + Ph*Vl (2 MMAs).
// ---------------------------------------------------------------------------
#define SROW 72   // smem row stride (fp16 units)

__global__ void __launch_bounds__(128, 2)
flash_attn_mma(int dummy)
{
    __shared__ __half sKh[64 * SROW];
    __shared__ __half sVh[64 * SROW];   // [dh][key]
    __shared__ __half sVl[64 * SROW];

    const int tid  = threadIdx.x;
    const int wid  = tid >> 5;
    const int lane = tid & 31;
    const int g    = lane >> 2;      // group row 0..7
    const int tg   = lane & 3;       // thread-in-group 0..3
    const int bh   = blockIdx.x;     // 0..15
    const int q0   = blockIdx.y * 64;
    const int r0   = q0 + wid * 16;  // this warp's first q row

    const __half* gKh = g_Kh + (size_t)bh * TT * DHH;
    const __half* gVh = g_Vth + (size_t)bh * DHH * TT;
    const __half* gVl = g_Vtl + (size_t)bh * DHH * TT;

    // ---- load Q A-fragments (fp16 single), scaled by 1/8 ----
    uint32_t qh[4][4];
    {
        const float* q0p = g_Q + ((size_t)bh * TT + r0 + g) * DHH;
        const float* q8p = q0p + 8 * DHH;
#pragma unroll
        for (int ks = 0; ks < 4; ks++) {
            int c0 = ks * 16 + tg * 2;
            int c1 = c0 + 8;
            float2 v00 = *(const float2*)(q0p + c0);
            float2 v10 = *(const float2*)(q8p + c0);
            float2 v01 = *(const float2*)(q0p + c1);
            float2 v11 = *(const float2*)(q8p + c1);
            qh[ks][0] = pack_f16x2(v00.x * 0.125f, v00.y * 0.125f);
            qh[ks][1] = pack_f16x2(v10.x * 0.125f, v10.y * 0.125f);
            qh[ks][2] = pack_f16x2(v01.x * 0.125f, v01.y * 0.125f);
            qh[ks][3] = pack_f16x2(v11.x * 0.125f, v11.y * 0.125f);
        }
    }

    const uint64_t* mrow0 = g_maskbits + (size_t)(r0 + g) * 64;
    const uint64_t* mrow8 = mrow0 + 8 * 64;

    float o[8][4];
#pragma unroll
    for (int nt = 0; nt < 8; nt++)
#pragma unroll
        for (int i = 0; i < 4; i++) o[nt][i] = 0.f;
    float l0 = 0.f, l1 = 0.f;

    for (int kt = 0; kt < TT / 64; kt++) {
        const int k0 = kt * 64;
        __syncthreads();   // previous tile's fragment reads done before overwrite

        // ---- stage K and V^T hi/lo (row-major, pad SROW): 3 x 512 chunks ----
#pragma unroll
        for (int it = 0; it < 3; it++) {
            int slot = tid + it * 128;        // 0..383  (x4 lanes of rows below)
            // 3 arrays x 64 rows x 8 chunks = 1536 chunks over 128 threads = 12 each;
            // do 4 chunks per iteration via j-unroll
            int arr = slot / 128;             // 0..2
            int rem = slot & 127;             // row pair index
            int r = rem >> 1, jbase = (rem & 1) * 4;
#pragma unroll
            for (int j = 0; j < 4; j++) {
                int c8 = jbase + j;
                if (arr == 0)
                    *(uint4*)&sKh[r * SROW + c8 * 8] = *(const uint4*)(gKh + (size_t)(k0 + r) * DHH + c8 * 8);
                else if (arr == 1)
                    *(uint4*)&sVh[r * SROW + c8 * 8] = *(const uint4*)(gVh + (size_t)r * TT + k0 + c8 * 8);
                else
                    *(uint4*)&sVl[r * SROW + c8 * 8] = *(const uint4*)(gVl + (size_t)r * TT + k0 + c8 * 8);
            }
        }
        __syncthreads();

        // ---- S = Qh Kh^T  (single fp16 MMA per fragment) ----
        float s[8][4];
#pragma unroll
        for (int nt = 0; nt < 8; nt++) {
#pragma unroll
            for (int i = 0; i < 4; i++) s[nt][i] = 0.f;
            const __half* rKh = &sKh[(nt * 8 + g) * SROW];
#pragma unroll
            for (int ks = 0; ks < 4; ks++) {
                int kk = ks * 16 + tg * 2;
                uint32_t bh0 = *(const uint32_t*)&rKh[kk];
                uint32_t bh1 = *(const uint32_t*)&rKh[kk + 8];
                mma16816h(s[nt], qh[ks], bh0, bh1);
            }
        }

        // ---- mask + exp + pack P (fp16 single) ----
        const uint64_t m0 = mrow0[kt];
        const uint64_t m8 = mrow8[kt];
        uint32_t pah[4][4];
#pragma unroll
        for (int nt = 0; nt < 8; nt++) {
            int cb = nt * 8 + tg * 2;
            float p0 = ((m0 >> cb) & 1ull)       ? __expf(s[nt][0]) : 0.f;
            float p1 = ((m0 >> (cb + 1)) & 1ull) ? __expf(s[nt][1]) : 0.f;
            float p2 = ((m8 >> cb) & 1ull)       ? __expf(s[nt][2]) : 0.f;
            float p3 = ((m8 >> (cb + 1)) & 1ull) ? __expf(s[nt][3]) : 0.f;
            l0 += p0 + p1;
            l1 += p2 + p3;
            int ks = nt >> 1;
            int hi = (nt & 1) ? 2 : 0;
            pah[ks][hi]     = pack_f16x2(p0, p1);
            pah[ks][hi + 1] = pack_f16x2(p2, p3);
        }

        // ---- O += P Vh + P Vl ----
#pragma unroll
        for (int nt = 0; nt < 8; nt++) {
            const __half* rVh = &sVh[(nt * 8 + g) * SROW];
            const __half* rVl = &sVl[(nt * 8 + g) * SROW];
#pragma unroll
            for (int ks = 0; ks < 4; ks++) {
                int kk = ks * 16 + tg * 2;
                uint32_t vh0 = *(const uint32_t*)&rVh[kk];
                uint32_t vh1 = *(const uint32_t*)&rVh[kk + 8];
                uint32_t vl0 = *(const uint32_t*)&rVl[kk];
                uint32_t vl1 = *(const uint32_t*)&rVl[kk + 8];
                mma16816h(o[nt], pah[ks], vh0, vh1);
                mma16816h(o[nt], pah[ks], vl0, vl1);
            }
        }
    }

    // ---- epilogue: reduce l, normalize, split bf16, store packed (b,t,D) ----
    l0 += __shfl_xor_sync(0xffffffffu, l0, 1);
    l0 += __shfl_xor_sync(0xffffffffu, l0, 2);
    l1 += __shfl_xor_sync(0xffffffffu, l1, 1);
    l1 += __shfl_xor_sync(0xffffffffu, l1, 2);
    float inv0 = 1.f / l0, inv1 = 1.f / l1;

    const int b = bh >> 3, h = bh & 7;
    size_t base0 = ((size_t)b * TT + (r0 + g)) * DD + h * DHH;
    size_t base8 = base0 + (size_t)8 * DD;
#pragma unroll
    for (int nt = 0; nt < 8; nt++) {
        int c = nt * 8 + tg * 2;
        float v0 = o[nt][0] * inv0, v1 = o[nt][1] * inv0;
        float v2 = o[nt][2] * inv1, v3 = o[nt][3] * inv1;
        float h0 = bf16_round(v0), h1 = bf16_round(v1);
        float h2 = bf16_round(v2), h3 = bf16_round(v3);
        *(uint32_t*)&g_Oh[base0 + c] = pack_bf16x2(h0, h1);
        *(uint32_t*)&g_Ol[base0 + c] = pack_bf16x2(v0 - h0, v1 - h1);
        *(uint32_t*)&g_Oh[base8 + c] = pack_bf16x2(h2, h3);
        *(uint32_t*)&g_Ol[base8 + c] = pack_bf16x2(v2 - h2, v3 - h3);
    }
}

// ---------------------------------------------------------------------------
// Launch.  Inputs identified BY SIZE.  Order: pack(1), split(2), qkv(3),
// flash(4) <- ncu-profiled slot, out(5).
// ---------------------------------------------------------------------------
extern "C" void kernel_launch(void* const* d_in, const int* in_sizes, int n_in,
                              void* d_out, int out_size)
{
    const float* x = nullptr;
    const float* Ws[4] = {nullptr, nullptr, nullptr, nullptr};
    const float* bs[4] = {nullptr, nullptr, nullptr, nullptr};
    const void*  mask = nullptr;
    int wc = 0, bc = 0;
    for (int i = 0; i < n_in; i++) {
        int sz = in_sizes[i];
        if (sz == TT * TT)            mask = d_in[i];
        else if (sz == MTOT * DD)     x = (const float*)d_in[i];
        else if (sz == DD * DD)       { if (wc < 4) Ws[wc++] = (const float*)d_in[i]; }
        else if (sz == DD)            { if (bc < 4) bs[bc++] = (const float*)d_in[i]; }
    }
    float* out = (float*)d_out;

    cudaFuncSetAttribute(gemm_qkv_mma, cudaFuncAttributeMaxDynamicSharedMemorySize, GEMM_SMEM);
    cudaFuncSetAttribute(gemm_out_mma, cudaFuncAttributeMaxDynamicSharedMemorySize, GEMM_SMEM);

    pack_mask_kernel<<<1024, 256>>>(mask);
    split_all_kernel<<<(MTOT * DD + 4 * WSZ) / 1024, 256>>>(x, Ws[0], Ws[1], Ws[2], Ws[3]);
    gemm_qkv_mma<<<dim3(DD / 64, MTOT / 128, 3), 256, GEMM_SMEM>>>(bs[0], bs[1], bs[2]);
    flash_attn_mma<<<dim3(BB * HH, TT / 64), 128>>>(0);
    gemm_out_mma<<<dim3(DD / 64, MTOT / 128), 256, GEMM_SMEM>>>(bs[3], out);
}

// round 16
// speedup vs baseline: 1.6306x; 1.2396x over previous
#include <cuda_runtime.h>
#include <cuda_bf16.h>
#include <cuda_fp16.h>
#include <cstdint>

// Problem constants
#define BB   2
#define TT   4096
#define DD   512
#define HH   8
#define DHH  64
#define MTOT (BB*TT)          // 8192
#define WSZ  (DD*DD)

// Scratch (allocation-free __device__ globals)
__device__ float g_Q[BB*HH*TT*DHH];                 // (bh, t, dh) fp32
__device__ __half g_Kh[BB*HH*TT*DHH];               // (bh, t, dh) fp16 (single)
__device__ __half g_Vth[BB*HH*DHH*TT];              // V TRANSPOSED: (bh, dh, t) fp16 (single)
__device__ __nv_bfloat16 g_Xh[MTOT*DD];             // x split hi (m, k)  [projections]
__device__ __nv_bfloat16 g_Xl[MTOT*DD];
__device__ __nv_bfloat16 g_Wh[4*WSZ];               // Wq,Wk,Wv,Wo split hi (k, n)
__device__ __nv_bfloat16 g_Wl[4*WSZ];
__device__ __nv_bfloat16 g_Oh[MTOT*DD];             // attention out split hi (m, D)
__device__ __nv_bfloat16 g_Ol[MTOT*DD];
__device__ uint64_t g_maskbits[TT * (TT / 64)];      // bit k of word (r, w): mask[r][w*64+k]

// ---------------------------------------------------------------------------
// Helpers
// ---------------------------------------------------------------------------
__device__ __forceinline__ float bf16_round(float x) {
    return __bfloat162float(__float2bfloat16(x));
}
__device__ __forceinline__ uint32_t pack_bf16x2(float a, float b) {   // a -> low half
    uint32_t r;
    asm("cvt.rn.satfinite.bf16x2.f32 %0, %1, %2;" : "=r"(r) : "f"(b), "f"(a));
    return r;
}
__device__ __forceinline__ uint32_t pack_f16x2(float a, float b) {    // a -> low half
    uint32_t r;
    asm("cvt.rn.f16x2.f32 %0, %1, %2;" : "=r"(r) : "f"(b), "f"(a));
    return r;
}
// D += A * B  (m16n8k16, row.col, bf16 in, f32 acc)
__device__ __forceinline__ void mma16816(float* d, const uint32_t* a, uint32_t b0, uint32_t b1) {
    asm volatile("mma.sync.aligned.m16n8k16.row.col.f32.bf16.bf16.f32 "
        "{%0,%1,%2,%3}, {%4,%5,%6,%7}, {%8,%9}, {%0,%1,%2,%3};"
        : "+f"(d[0]), "+f"(d[1]), "+f"(d[2]), "+f"(d[3])
        : "r"(a[0]), "r"(a[1]), "r"(a[2]), "r"(a[3]), "r"(b0), "r"(b1));
}
// D += A * B  (m16n8k16, row.col, fp16 in, f32 acc)
__device__ __forceinline__ void mma16816h(float* d, const uint32_t* a, uint32_t b0, uint32_t b1) {
    asm volatile("mma.sync.aligned.m16n8k16.row.col.f32.f16.f16.f32 "
        "{%0,%1,%2,%3}, {%4,%5,%6,%7}, {%8,%9}, {%0,%1,%2,%3};"
        : "+f"(d[0]), "+f"(d[1]), "+f"(d[2]), "+f"(d[3])
        : "r"(a[0]), "r"(a[1]), "r"(a[2]), "r"(a[3]), "r"(b0), "r"(b1));
}
__device__ __forceinline__ uint32_t smem_u32(const void* p) {
    uint32_t a;
    asm("{ .reg .u64 t; cvta.to.shared.u64 t, %1; cvt.u32.u64 %0, t; }" : "=r"(a) : "l"(p));
    return a;
}
__device__ __forceinline__ void cpa16(uint32_t d, const void* s) {
    asm volatile("cp.async.cg.shared.global [%0], [%1], 16;" :: "r"(d), "l"(s));
}
__device__ __forceinline__ void cpa_commit() {
    asm volatile("cp.async.commit_group;" ::: "memory");
}
template<int N> __device__ __forceinline__ void cpa_wait() {
    asm volatile("cp.async.wait_group %0;" :: "n"(N) : "memory");
}
__device__ __forceinline__ void ldsm4(uint32_t* d, uint32_t a) {
    asm volatile("ldmatrix.sync.aligned.m8n8.x4.shared.b16 {%0,%1,%2,%3}, [%4];"
        : "=r"(d[0]), "=r"(d[1]), "=r"(d[2]), "=r"(d[3]) : "r"(a));
}
__device__ __forceinline__ void ldsm4t(uint32_t* d, uint32_t a) {
    asm volatile("ldmatrix.sync.aligned.m8n8.x4.trans.shared.b16 {%0,%1,%2,%3}, [%4];"
        : "=r"(d[0]), "=r"(d[1]), "=r"(d[2]), "=r"(d[3]) : "r"(a));
}

// ---------------------------------------------------------------------------
// Mask pack with inline dtype detection (validated round 12)
// ---------------------------------------------------------------------------
__device__ __forceinline__ bool hw_ok(uint32_t h) {
    return h == 0u || h == 1u || h == 0x3F80u;
}
__global__ void pack_mask_kernel(const void* __restrict__ mask_raw)
{
    const uint32_t* m = (const uint32_t*)mask_raw;
    const int tid = threadIdx.x;
    bool w4 = true, w2 = true;
    for (int i = tid; i < 1024; i += 256) {
        uint32_t w = m[i];
        if (!(w == 0u || w == 1u || w == 0x3F800000u)) w4 = false;
        if (!(hw_ok(w & 0xFFFFu) && hw_ok(w >> 16)))   w2 = false;
    }
    int all4 = __syncthreads_and(w4 ? 1 : 0);
    int all2 = __syncthreads_and(w2 ? 1 : 0);
    const int mode = all4 ? 2 : (all2 ? 1 : 0);

    int idx = blockIdx.x * 256 + tid;      // 0 .. 262143
    int row = idx >> 6;
    int wi  = idx & 63;
    uint64_t bits = 0;
    if (mode == 2) {
        const uint4* p = (const uint4*)((const uint32_t*)mask_raw + (size_t)row * TT + wi * 64);
#pragma unroll
        for (int w = 0; w < 16; w++) {
            uint4 v = p[w];
            uint64_t f = (uint64_t)((v.x != 0u) | ((v.y != 0u) << 1)
                                  | ((v.z != 0u) << 2) | ((v.w != 0u) << 3));
            bits |= f << (w * 4);
        }
    } else if (mode == 1) {
        const uint16_t* p = (const uint16_t*)mask_raw + (size_t)row * TT + wi * 64;
#pragma unroll
        for (int k = 0; k < 64; k++)
            bits |= (uint64_t)(p[k] != 0) << k;
    } else {
        const uint8_t* p = (const uint8_t*)mask_raw + (size_t)row * TT + wi * 64;
#pragma unroll
        for (int k = 0; k < 64; k++)
            bits |= (uint64_t)(p[k] != 0) << k;
    }
    g_maskbits[idx] = bits;
}

// ---------------------------------------------------------------------------
// Merged split: x then the 4 weights, fp32 -> bf16 hi/lo (validated round 12)
// ---------------------------------------------------------------------------
__global__ void split_all_kernel(const float* __restrict__ x,
                                 const float* __restrict__ W0, const float* __restrict__ W1,
                                 const float* __restrict__ W2, const float* __restrict__ W3)
{
    size_t gid = ((size_t)blockIdx.x * 256 + threadIdx.x) * 4;
    const float* src;
    __nv_bfloat16 *dsth, *dstl;
    if (gid < (size_t)MTOT * DD) {
        src = x + gid; dsth = g_Xh + gid; dstl = g_Xl + gid;
    } else {
        size_t w = gid - (size_t)MTOT * DD;
        int wi = (int)(w / WSZ);
        size_t wo = w % WSZ;
        const float* W = (wi == 0) ? W0 : (wi == 1) ? W1 : (wi == 2) ? W2 : W3;
        src = W + wo; dsth = g_Wh + w; dstl = g_Wl + w;
    }
    float4 v = *(const float4*)src;
    float h0 = bf16_round(v.x), h1 = bf16_round(v.y);
    float h2 = bf16_round(v.z), h3 = bf16_round(v.w);
    *(uint2*)dsth = make_uint2(pack_bf16x2(h0, h1), pack_bf16x2(h2, h3));
    *(uint2*)dstl = make_uint2(pack_bf16x2(v.x - h0, v.y - h1), pack_bf16x2(v.z - h2, v.w - h3));
}

// ---------------------------------------------------------------------------
// Shared GEMM core (unchanged, validated round 9)
// ---------------------------------------------------------------------------
#define SMA_SZ (2*2*128*40)
#define SMB_SZ (2*2*32*72)
#define GEMM_SMEM ((SMA_SZ + SMB_SZ) * 2)   // bytes = 59392

__device__ __forceinline__ void gemm_core(
    const __nv_bfloat16* __restrict__ Ah, const __nv_bfloat16* __restrict__ Al,
    const __nv_bfloat16* __restrict__ Bh, const __nv_bfloat16* __restrict__ Bl,
    int m0, int n0, float c[2][4][4])
{
    extern __shared__ __nv_bfloat16 sm[];
    const int tid = threadIdx.x;
    const int wid = tid >> 5, lane = tid & 31;
    const int wr = wid >> 1, wc = wid & 1;
    const int quad = lane >> 3, r8 = lane & 7;

#pragma unroll
    for (int mt = 0; mt < 2; mt++)
#pragma unroll
        for (int nt = 0; nt < 4; nt++)
#pragma unroll
            for (int e = 0; e < 4; e++) c[mt][nt][e] = 0.f;

    auto preload = [&](int buf, int k0) {
#pragma unroll
        for (int i = 0; i < 6; i++) {
            int ch = tid + i * 256;            // 0..1535
            if (ch < 1024) {                   // A: 2 x 128 rows x 4 chunks
                int h = ch >> 9, rem = ch & 511;
                int row = rem >> 2, kc = rem & 3;
                uint32_t dst = smem_u32(&sm[((buf * 2 + h) * 128 + row) * 40 + kc * 8]);
                cpa16(dst, (h ? Al : Ah) + (size_t)(m0 + row) * DD + k0 + kc * 8);
            } else {                           // B: 2 x 32 rows x 8 chunks
                int d2 = ch - 1024;
                int h = d2 >> 8, rem = d2 & 255;
                int row = rem >> 3, nc = rem & 7;
                uint32_t dst = smem_u32(&sm[SMA_SZ + ((buf * 2 + h) * 32 + row) * 72 + nc * 8]);
                cpa16(dst, (h ? Bl : Bh) + (size_t)(k0 + row) * DD + n0 + nc * 8);
            }
        }
        cpa_commit();
    };

    preload(0, 0);
    for (int s = 0; s < 16; s++) {
        if (s + 1 < 16) { preload((s + 1) & 1, (s + 1) * 32); cpa_wait<1>(); }
        else            { cpa_wait<0>(); }
        __syncthreads();
        const int buf = s & 1;

#pragma unroll
        for (int chunk = 0; chunk < 2; chunk++) {
            uint32_t ah0[4], al0[4], ah1[4], al1[4];
            int arow0 = wr * 32 + (quad & 1) * 8 + r8;
            int acol  = chunk * 16 + (quad >> 1) * 8;
            ldsm4(ah0, smem_u32(&sm[((buf * 2 + 0) * 128 + arow0) * 40 + acol]));
            ldsm4(al0, smem_u32(&sm[((buf * 2 + 1) * 128 + arow0) * 40 + acol]));
            ldsm4(ah1, smem_u32(&sm[((buf * 2 + 0) * 128 + arow0 + 16) * 40 + acol]));
            ldsm4(al1, smem_u32(&sm[((buf * 2 + 1) * 128 + arow0 + 16) * 40 + acol]));
#pragma unroll
            for (int ntp = 0; ntp < 2; ntp++) {
                uint32_t bhf[4], blf[4];
                int brow = chunk * 16 + (quad & 1) * 8 + r8;
                int bcol = wc * 32 + ntp * 16 + (quad >> 1) * 8;
                ldsm4t(bhf, smem_u32(&sm[SMA_SZ + ((buf * 2 + 0) * 32 + brow) * 72 + bcol]));
                ldsm4t(blf, smem_u32(&sm[SMA_SZ + ((buf * 2 + 1) * 32 + brow) * 72 + bcol]));
#pragma unroll
                for (int half = 0; half < 2; half++) {
                    int nt = ntp * 2 + half;
                    uint32_t b0 = bhf[half * 2], b1 = bhf[half * 2 + 1];
                    uint32_t bl0 = blf[half * 2], bl1 = blf[half * 2 + 1];
                    mma16816(c[0][nt], ah0, b0, b1);
                    mma16816(c[0][nt], al0, b0, b1);
                    mma16816(c[0][nt], ah0, bl0, bl1);
                    mma16816(c[1][nt], ah1, b0, b1);
                    mma16816(c[1][nt], al1, b0, b1);
                    mma16816(c[1][nt], ah1, bl0, bl1);
                }
            }
        }
        __syncthreads();
    }
}

// ---------------------------------------------------------------------------
// QKV projection via HMMA.  Epilogue: Q fp32; K fp16 single; V fp16 single (T).
// ---------------------------------------------------------------------------
__global__ void __launch_bounds__(256, 2)
gemm_qkv_mma(const float* __restrict__ bq, const float* __restrict__ bk,
             const float* __restrict__ bv)
{
    const int mode = blockIdx.z;
    const int m0 = blockIdx.y * 128, n0 = blockIdx.x * 64;
    const float* bias = (mode == 0) ? bq : (mode == 1) ? bk : bv;

    float c[2][4][4];
    gemm_core(g_Xh, g_Xl, g_Wh + (size_t)mode * WSZ, g_Wl + (size_t)mode * WSZ, m0, n0, c);

    const int tid = threadIdx.x, wid = tid >> 5, lane = tid & 31;
    const int wr = wid >> 1, wc = wid & 1, g = lane >> 2, tg = lane & 3;

#pragma unroll
    for (int mt = 0; mt < 2; mt++) {
#pragma unroll
        for (int nt = 0; nt < 4; nt++) {
            int n = n0 + wc * 32 + nt * 8 + tg * 2;
            int h = n >> 6, dh = n & 63;
            float b0v = bias[n], b1v = bias[n + 1];
#pragma unroll
            for (int e = 0; e < 2; e++) {
                int m = m0 + wr * 32 + mt * 16 + g + e * 8;
                int b = m >> 12, t = m & 4095;
                float v0 = c[mt][nt][e * 2 + 0] + b0v;
                float v1 = c[mt][nt][e * 2 + 1] + b1v;
                size_t bhh = (size_t)b * HH + h;
                if (mode == 0) {
                    *(float2*)&g_Q[(bhh * TT + t) * DHH + dh] = make_float2(v0, v1);
                } else if (mode == 1) {
                    size_t idx = (bhh * TT + t) * DHH + dh;
                    *(uint32_t*)&g_Kh[idx] = pack_f16x2(v0, v1);
                } else {
                    size_t i0 = (bhh * DHH + dh) * TT + t;
                    size_t i1 = (bhh * DHH + dh + 1) * TT + t;
                    g_Vth[i0] = __float2half_rn(v0);
                    g_Vth[i1] = __float2half_rn(v1);
                }
            }
        }
    }
}

// ---------------------------------------------------------------------------
// Output projection via HMMA (unchanged, validated round 9)
// ---------------------------------------------------------------------------
__global__ void __launch_bounds__(256, 2)
gemm_out_mma(const float* __restrict__ bo, float* __restrict__ out)
{
    const int m0 = blockIdx.y * 128, n0 = blockIdx.x * 64;
    float c[2][4][4];
    gemm_core(g_Oh, g_Ol, g_Wh + 3 * (size_t)WSZ, g_Wl + 3 * (size_t)WSZ, m0, n0, c);

    const int tid = threadIdx.x, wid = tid >> 5, lane = tid & 31;
    const int wr = wid >> 1, wc = wid & 1, g = lane >> 2, tg = lane & 3;

#pragma unroll
    for (int mt = 0; mt < 2; mt++) {
#pragma unroll
        for (int nt = 0; nt < 4; nt++) {
            int n = n0 + wc * 32 + nt * 8 + tg * 2;
            float b0v = bo[n], b1v = bo[n + 1];
#pragma unroll
            for (int e = 0; e < 2; e++) {
                int m = m0 + wr * 32 + mt * 16 + g + e * 8;
                float v0 = c[mt][nt][e * 2 + 0] + b0v;
                float v1 = c[mt][nt][e * 2 + 1] + b1v;
                *(float2*)&out[(size_t)m * DD + n] = make_float2(v0, v1);
            }
        }
    }
}

// ---------------------------------------------------------------------------
// Kernel: flash attention.  Round-14 structure with V-lo removed:
//   S = Qh*Kh (1 fp16 MMA), O += Ph*Vh (1 fp16 MMA).
// smem 18.4 KB, 3 CTAs/SM target.
// ---------------------------------------------------------------------------
#define SROW 72   // smem row stride (fp16 units)

__global__ void __launch_bounds__(128, 3)
flash_attn_mma(int dummy)
{
    __shared__ __half sKh[64 * SROW];
    __shared__ __half sVh[64 * SROW];   // [dh][key]

    const int tid  = threadIdx.x;
    const int wid  = tid >> 5;
    const int lane = tid & 31;
    const int g    = lane >> 2;      // group row 0..7
    const int tg   = lane & 3;       // thread-in-group 0..3
    const int bh   = blockIdx.x;     // 0..15
    const int q0   = blockIdx.y * 64;
    const int r0   = q0 + wid * 16;  // this warp's first q row

    const __half* gKh = g_Kh + (size_t)bh * TT * DHH;
    const __half* gVh = g_Vth + (size_t)bh * DHH * TT;

    // ---- load Q A-fragments (fp16 single), scaled by 1/8 ----
    uint32_t qh[4][4];
    {
        const float* q0p = g_Q + ((size_t)bh * TT + r0 + g) * DHH;
        const float* q8p = q0p + 8 * DHH;
#pragma unroll
        for (int ks = 0; ks < 4; ks++) {
            int c0 = ks * 16 + tg * 2;
            int c1 = c0 + 8;
            float2 v00 = *(const float2*)(q0p + c0);
            float2 v10 = *(const float2*)(q8p + c0);
            float2 v01 = *(const float2*)(q0p + c1);
            float2 v11 = *(const float2*)(q8p + c1);
            qh[ks][0] = pack_f16x2(v00.x * 0.125f, v00.y * 0.125f);
            qh[ks][1] = pack_f16x2(v10.x * 0.125f, v10.y * 0.125f);
            qh[ks][2] = pack_f16x2(v01.x * 0.125f, v01.y * 0.125f);
            qh[ks][3] = pack_f16x2(v11.x * 0.125f, v11.y * 0.125f);
        }
    }

    const uint64_t* mrow0 = g_maskbits + (size_t)(r0 + g) * 64;
    const uint64_t* mrow8 = mrow0 + 8 * 64;

    float o[8][4];
#pragma unroll
    for (int nt = 0; nt < 8; nt++)
#pragma unroll
        for (int i = 0; i < 4; i++) o[nt][i] = 0.f;
    float l0 = 0.f, l1 = 0.f;

    for (int kt = 0; kt < TT / 64; kt++) {
        const int k0 = kt * 64;
        __syncthreads();   // previous tile's fragment reads done before overwrite

        // ---- stage K and V^T (row-major, pad SROW): 2 arrays x 512 chunks ----
#pragma unroll
        for (int it = 0; it < 2; it++) {
            int slot = tid + it * 128;        // 0..255
            int arr = slot >> 7;              // 0:Kh 1:Vh
            int rem = slot & 127;
            int r = rem >> 1, jbase = (rem & 1) * 4;
#pragma unroll
            for (int j = 0; j < 4; j++) {
                int c8 = jbase + j;
                if (arr == 0)
                    *(uint4*)&sKh[r * SROW + c8 * 8] = *(const uint4*)(gKh + (size_t)(k0 + r) * DHH + c8 * 8);
                else
                    *(uint4*)&sVh[r * SROW + c8 * 8] = *(const uint4*)(gVh + (size_t)r * TT + k0 + c8 * 8);
            }
        }
        __syncthreads();

        // ---- S = Qh Kh^T ----
        float s[8][4];
#pragma unroll
        for (int nt = 0; nt < 8; nt++) {
#pragma unroll
            for (int i = 0; i < 4; i++) s[nt][i] = 0.f;
            const __half* rKh = &sKh[(nt * 8 + g) * SROW];
#pragma unroll
            for (int ks = 0; ks < 4; ks++) {
                int kk = ks * 16 + tg * 2;
                uint32_t bh0 = *(const uint32_t*)&rKh[kk];
                uint32_t bh1 = *(const uint32_t*)&rKh[kk + 8];
                mma16816h(s[nt], qh[ks], bh0, bh1);
            }
        }

        // ---- mask + exp + pack P (fp16 single) ----
        const uint64_t m0 = mrow0[kt];
        const uint64_t m8 = mrow8[kt];
        uint32_t pah[4][4];
#pragma unroll
        for (int nt = 0; nt < 8; nt++) {
            int cb = nt * 8 + tg * 2;
            float p0 = ((m0 >> cb) & 1ull)       ? __expf(s[nt][0]) : 0.f;
            float p1 = ((m0 >> (cb + 1)) & 1ull) ? __expf(s[nt][1]) : 0.f;
            float p2 = ((m8 >> cb) & 1ull)       ? __expf(s[nt][2]) : 0.f;
            float p3 = ((m8 >> (cb + 1)) & 1ull) ? __expf(s[nt][3]) : 0.f;
            l0 += p0 + p1;
            l1 += p2 + p3;
            int ks = nt >> 1;
            int hi = (nt & 1) ? 2 : 0;
            pah[ks][hi]     = pack_f16x2(p0, p1);
            pah[ks][hi + 1] = pack_f16x2(p2, p3);
        }

        // ---- O += P Vh ----
#pragma unroll
        for (int nt = 0; nt < 8; nt++) {
            const __half* rVh = &sVh[(nt * 8 + g) * SROW];
#pragma unroll
            for (int ks = 0; ks < 4; ks++) {
                int kk = ks * 16 + tg * 2;
                uint32_t vh0 = *(const uint32_t*)&rVh[kk];
                uint32_t vh1 = *(const uint32_t*)&rVh[kk + 8];
                mma16816h(o[nt], pah[ks], vh0, vh1);
            }
        }
    }

    // ---- epilogue: reduce l, normalize, split bf16, store packed (b,t,D) ----
    l0 += __shfl_xor_sync(0xffffffffu, l0, 1);
    l0 += __shfl_xor_sync(0xffffffffu, l0, 2);
    l1 += __shfl_xor_sync(0xffffffffu, l1, 1);
    l1 += __shfl_xor_sync(0xffffffffu, l1, 2);
    float inv0 = 1.f / l0, inv1 = 1.f / l1;

    const int b = bh >> 3, h = bh & 7;
    size_t base0 = ((size_t)b * TT + (r0 + g)) * DD + h * DHH;
    size_t base8 = base0 + (size_t)8 * DD;
#pragma unroll
    for (int nt = 0; nt < 8; nt++) {
        int c = nt * 8 + tg * 2;
        float v0 = o[nt][0] * inv0, v1 = o[nt][1] * inv0;
        float v2 = o[nt][2] * inv1, v3 = o[nt][3] * inv1;
        float h0 = bf16_round(v0), h1 = bf16_round(v1);
        float h2 = bf16_round(v2), h3 = bf16_round(v3);
        *(uint32_t*)&g_Oh[base0 + c] = pack_bf16x2(h0, h1);
        *(uint32_t*)&g_Ol[base0 + c] = pack_bf16x2(v0 - h0, v1 - h1);
        *(uint32_t*)&g_Oh[base8 + c] = pack_bf16x2(h2, h3);
        *(uint32_t*)&g_Ol[base8 + c] = pack_bf16x2(v2 - h2, v3 - h3);
    }
}

// ---------------------------------------------------------------------------
// Launch.  Inputs identified BY SIZE.
// ---------------------------------------------------------------------------
extern "C" void kernel_launch(void* const* d_in, const int* in_sizes, int n_in,
                              void* d_out, int out_size)
{
    const float* x = nullptr;
    const float* Ws[4] = {nullptr, nullptr, nullptr, nullptr};
    const float* bs[4] = {nullptr, nullptr, nullptr, nullptr};
    const void*  mask = nullptr;
    int wc = 0, bc = 0;
    for (int i = 0; i < n_in; i++) {
        int sz = in_sizes[i];
        if (sz == TT * TT)            mask = d_in[i];
        else if (sz == MTOT * DD)     x = (const float*)d_in[i];
        else if (sz == DD * DD)       { if (wc < 4) Ws[wc++] = (const float*)d_in[i]; }
        else if (sz == DD)            { if (bc < 4) bs[bc++] = (const float*)d_in[i]; }
    }
    float* out = (float*)d_out;

    cudaFuncSetAttribute(gemm_qkv_mma, cudaFuncAttributeMaxDynamicSharedMemorySize, GEMM_SMEM);
    cudaFuncSetAttribute(gemm_out_mma, cudaFuncAttributeMaxDynamicSharedMemorySize, GEMM_SMEM);

    pack_mask_kernel<<<1024, 256>>>(mask);
    split_all_kernel<<<(MTOT * DD + 4 * WSZ) / 1024, 256>>>(x, Ws[0], Ws[1], Ws[2], Ws[3]);
    gemm_qkv_mma<<<dim3(DD / 64, MTOT / 128, 3), 256, GEMM_SMEM>>>(bs[0], bs[1], bs[2]);
    flash_attn_mma<<<dim3(BB * HH, TT / 64), 128>>>(0);
    gemm_out_mma<<<dim3(DD / 64, MTOT / 128), 256, GEMM_SMEM>>>(bs[3], out);
}

// round 17
// speedup vs baseline: 1.8767x; 1.1509x over previous
#include <cuda_runtime.h>
#include <cuda_bf16.h>
#include <cuda_fp16.h>
#include <cstdint>

// Problem constants
#define BB   2
#define TT   4096
#define DD   512
#define HH   8
#define DHH  64
#define MTOT (BB*TT)          // 8192
#define WSZ  (DD*DD)

// Scratch (allocation-free __device__ globals)
__device__ float g_Q[BB*HH*TT*DHH];                 // (bh, t, dh) fp32
__device__ __half g_Kh[BB*HH*TT*DHH];               // (bh, t, dh) fp16 (single)
__device__ __half g_Vth[BB*HH*DHH*TT];              // V TRANSPOSED: (bh, dh, t) fp16 (single)
__device__ __nv_bfloat16 g_Xh[MTOT*DD];             // x split hi (m, k)  [projections]
__device__ __nv_bfloat16 g_Xl[MTOT*DD];
__device__ __nv_bfloat16 g_Wh[4*WSZ];               // Wq,Wk,Wv,Wo split hi (k, n)
__device__ __nv_bfloat16 g_Wl[4*WSZ];
__device__ __nv_bfloat16 g_Oh[MTOT*DD];             // attention out split hi (m, D)
__device__ __nv_bfloat16 g_Ol[MTOT*DD];
__device__ uint64_t g_maskbits[TT * (TT / 64)];      // bit k of word (r, w): mask[r][w*64+k]

// ---------------------------------------------------------------------------
// Helpers
// ---------------------------------------------------------------------------
__device__ __forceinline__ float bf16_round(float x) {
    return __bfloat162float(__float2bfloat16(x));
}
__device__ __forceinline__ uint32_t pack_bf16x2(float a, float b) {   // a -> low half
    uint32_t r;
    asm("cvt.rn.satfinite.bf16x2.f32 %0, %1, %2;" : "=r"(r) : "f"(b), "f"(a));
    return r;
}
__device__ __forceinline__ uint32_t pack_f16x2(float a, float b) {    // a -> low half
    uint32_t r;
    asm("cvt.rn.f16x2.f32 %0, %1, %2;" : "=r"(r) : "f"(b), "f"(a));
    return r;
}
// D += A * B  (m16n8k16, row.col, bf16 in, f32 acc)
__device__ __forceinline__ void mma16816(float* d, const uint32_t* a, uint32_t b0, uint32_t b1) {
    asm volatile("mma.sync.aligned.m16n8k16.row.col.f32.bf16.bf16.f32 "
        "{%0,%1,%2,%3}, {%4,%5,%6,%7}, {%8,%9}, {%0,%1,%2,%3};"
        : "+f"(d[0]), "+f"(d[1]), "+f"(d[2]), "+f"(d[3])
        : "r"(a[0]), "r"(a[1]), "r"(a[2]), "r"(a[3]), "r"(b0), "r"(b1));
}
// D += A * B  (m16n8k16, row.col, fp16 in, f32 acc)
__device__ __forceinline__ void mma16816h(float* d, const uint32_t* a, uint32_t b0, uint32_t b1) {
    asm volatile("mma.sync.aligned.m16n8k16.row.col.f32.f16.f16.f32 "
        "{%0,%1,%2,%3}, {%4,%5,%6,%7}, {%8,%9}, {%0,%1,%2,%3};"
        : "+f"(d[0]), "+f"(d[1]), "+f"(d[2]), "+f"(d[3])
        : "r"(a[0]), "r"(a[1]), "r"(a[2]), "r"(a[3]), "r"(b0), "r"(b1));
}
__device__ __forceinline__ uint32_t smem_u32(const void* p) {
    uint32_t a;
    asm("{ .reg .u64 t; cvta.to.shared.u64 t, %1; cvt.u32.u64 %0, t; }" : "=r"(a) : "l"(p));
    return a;
}
__device__ __forceinline__ void cpa16(uint32_t d, const void* s) {
    asm volatile("cp.async.cg.shared.global [%0], [%1], 16;" :: "r"(d), "l"(s));
}
__device__ __forceinline__ void cpa_commit() {
    asm volatile("cp.async.commit_group;" ::: "memory");
}
template<int N> __device__ __forceinline__ void cpa_wait() {
    asm volatile("cp.async.wait_group %0;" :: "n"(N) : "memory");
}
__device__ __forceinline__ void ldsm4(uint32_t* d, uint32_t a) {
    asm volatile("ldmatrix.sync.aligned.m8n8.x4.shared.b16 {%0,%1,%2,%3}, [%4];"
        : "=r"(d[0]), "=r"(d[1]), "=r"(d[2]), "=r"(d[3]) : "r"(a));
}
__device__ __forceinline__ void ldsm4t(uint32_t* d, uint32_t a) {
    asm volatile("ldmatrix.sync.aligned.m8n8.x4.trans.shared.b16 {%0,%1,%2,%3}, [%4];"
        : "=r"(d[0]), "=r"(d[1]), "=r"(d[2]), "=r"(d[3]) : "r"(a));
}

// ---------------------------------------------------------------------------
// Mask pack with inline dtype detection (validated round 12)
// ---------------------------------------------------------------------------
__device__ __forceinline__ bool hw_ok(uint32_t h) {
    return h == 0u || h == 1u || h == 0x3F80u;
}
__global__ void pack_mask_kernel(const void* __restrict__ mask_raw)
{
    const uint32_t* m = (const uint32_t*)mask_raw;
    const int tid = threadIdx.x;
    bool w4 = true, w2 = true;
    for (int i = tid; i < 1024; i += 256) {
        uint32_t w = m[i];
        if (!(w == 0u || w == 1u || w == 0x3F800000u)) w4 = false;
        if (!(hw_ok(w & 0xFFFFu) && hw_ok(w >> 16)))   w2 = false;
    }
    int all4 = __syncthreads_and(w4 ? 1 : 0);
    int all2 = __syncthreads_and(w2 ? 1 : 0);
    const int mode = all4 ? 2 : (all2 ? 1 : 0);

    int idx = blockIdx.x * 256 + tid;      // 0 .. 262143
    int row = idx >> 6;
    int wi  = idx & 63;
    uint64_t bits = 0;
    if (mode == 2) {
        const uint4* p = (const uint4*)((const uint32_t*)mask_raw + (size_t)row * TT + wi * 64);
#pragma unroll
        for (int w = 0; w < 16; w++) {
            uint4 v = p[w];
            uint64_t f = (uint64_t)((v.x != 0u) | ((v.y != 0u) << 1)
                                  | ((v.z != 0u) << 2) | ((v.w != 0u) << 3));
            bits |= f << (w * 4);
        }
    } else if (mode == 1) {
        const uint16_t* p = (const uint16_t*)mask_raw + (size_t)row * TT + wi * 64;
#pragma unroll
        for (int k = 0; k < 64; k++)
            bits |= (uint64_t)(p[k] != 0) << k;
    } else {
        const uint8_t* p = (const uint8_t*)mask_raw + (size_t)row * TT + wi * 64;
#pragma unroll
        for (int k = 0; k < 64; k++)
            bits |= (uint64_t)(p[k] != 0) << k;
    }
    g_maskbits[idx] = bits;
}

// ---------------------------------------------------------------------------
// Merged split: x then the 4 weights, fp32 -> bf16 hi/lo (validated round 12)
// ---------------------------------------------------------------------------
__global__ void split_all_kernel(const float* __restrict__ x,
                                 const float* __restrict__ W0, const float* __restrict__ W1,
                                 const float* __restrict__ W2, const float* __restrict__ W3)
{
    size_t gid = ((size_t)blockIdx.x * 256 + threadIdx.x) * 4;
    const float* src;
    __nv_bfloat16 *dsth, *dstl;
    if (gid < (size_t)MTOT * DD) {
        src = x + gid; dsth = g_Xh + gid; dstl = g_Xl + gid;
    } else {
        size_t w = gid - (size_t)MTOT * DD;
        int wi = (int)(w / WSZ);
        size_t wo = w % WSZ;
        const float* W = (wi == 0) ? W0 : (wi == 1) ? W1 : (wi == 2) ? W2 : W3;
        src = W + wo; dsth = g_Wh + w; dstl = g_Wl + w;
    }
    float4 v = *(const float4*)src;
    float h0 = bf16_round(v.x), h1 = bf16_round(v.y);
    float h2 = bf16_round(v.z), h3 = bf16_round(v.w);
    *(uint2*)dsth = make_uint2(pack_bf16x2(h0, h1), pack_bf16x2(h2, h3));
    *(uint2*)dstl = make_uint2(pack_bf16x2(v.x - h0, v.y - h1), pack_bf16x2(v.z - h2, v.w - h3));
}

// ---------------------------------------------------------------------------
// Shared GEMM core (unchanged, validated round 9)
// ---------------------------------------------------------------------------
#define SMA_SZ (2*2*128*40)
#define SMB_SZ (2*2*32*72)
#define GEMM_SMEM ((SMA_SZ + SMB_SZ) * 2)   // bytes = 59392

__device__ __forceinline__ void gemm_core(
    const __nv_bfloat16* __restrict__ Ah, const __nv_bfloat16* __restrict__ Al,
    const __nv_bfloat16* __restrict__ Bh, const __nv_bfloat16* __restrict__ Bl,
    int m0, int n0, float c[2][4][4])
{
    extern __shared__ __nv_bfloat16 sm[];
    const int tid = threadIdx.x;
    const int wid = tid >> 5, lane = tid & 31;
    const int wr = wid >> 1, wc = wid & 1;
    const int quad = lane >> 3, r8 = lane & 7;

#pragma unroll
    for (int mt = 0; mt < 2; mt++)
#pragma unroll
        for (int nt = 0; nt < 4; nt++)
#pragma unroll
            for (int e = 0; e < 4; e++) c[mt][nt][e] = 0.f;

    auto preload = [&](int buf, int k0) {
#pragma unroll
        for (int i = 0; i < 6; i++) {
            int ch = tid + i * 256;            // 0..1535
            if (ch < 1024) {                   // A: 2 x 128 rows x 4 chunks
                int h = ch >> 9, rem = ch & 511;
                int row = rem >> 2, kc = rem & 3;
                uint32_t dst = smem_u32(&sm[((buf * 2 + h) * 128 + row) * 40 + kc * 8]);
                cpa16(dst, (h ? Al : Ah) + (size_t)(m0 + row) * DD + k0 + kc * 8);
            } else {                           // B: 2 x 32 rows x 8 chunks
                int d2 = ch - 1024;
                int h = d2 >> 8, rem = d2 & 255;
                int row = rem >> 3, nc = rem & 7;
                uint32_t dst = smem_u32(&sm[SMA_SZ + ((buf * 2 + h) * 32 + row) * 72 + nc * 8]);
                cpa16(dst, (h ? Bl : Bh) + (size_t)(k0 + row) * DD + n0 + nc * 8);
            }
        }
        cpa_commit();
    };

    preload(0, 0);
    for (int s = 0; s < 16; s++) {
        if (s + 1 < 16) { preload((s + 1) & 1, (s + 1) * 32); cpa_wait<1>(); }
        else            { cpa_wait<0>(); }
        __syncthreads();
        const int buf = s & 1;

#pragma unroll
        for (int chunk = 0; chunk < 2; chunk++) {
            uint32_t ah0[4], al0[4], ah1[4], al1[4];
            int arow0 = wr * 32 + (quad & 1) * 8 + r8;
            int acol  = chunk * 16 + (quad >> 1) * 8;
            ldsm4(ah0, smem_u32(&sm[((buf * 2 + 0) * 128 + arow0) * 40 + acol]));
            ldsm4(al0, smem_u32(&sm[((buf * 2 + 1) * 128 + arow0) * 40 + acol]));
            ldsm4(ah1, smem_u32(&sm[((buf * 2 + 0) * 128 + arow0 + 16) * 40 + acol]));
            ldsm4(al1, smem_u32(&sm[((buf * 2 + 1) * 128 + arow0 + 16) * 40 + acol]));
#pragma unroll
            for (int ntp = 0; ntp < 2; ntp++) {
                uint32_t bhf[4], blf[4];
                int brow = chunk * 16 + (quad & 1) * 8 + r8;
                int bcol = wc * 32 + ntp * 16 + (quad >> 1) * 8;
                ldsm4t(bhf, smem_u32(&sm[SMA_SZ + ((buf * 2 + 0) * 32 + brow) * 72 + bcol]));
                ldsm4t(blf, smem_u32(&sm[SMA_SZ + ((buf * 2 + 1) * 32 + brow) * 72 + bcol]));
#pragma unroll
                for (int half = 0; half < 2; half++) {
                    int nt = ntp * 2 + half;
                    uint32_t b0 = bhf[half * 2], b1 = bhf[half * 2 + 1];
                    uint32_t bl0 = blf[half * 2], bl1 = blf[half * 2 + 1];
                    mma16816(c[0][nt], ah0, b0, b1);
                    mma16816(c[0][nt], al0, b0, b1);
                    mma16816(c[0][nt], ah0, bl0, bl1);
                    mma16816(c[1][nt], ah1, b0, b1);
                    mma16816(c[1][nt], al1, b0, b1);
                    mma16816(c[1][nt], ah1, bl0, bl1);
                }
            }
        }
        __syncthreads();
    }
}

// ---------------------------------------------------------------------------
// QKV projection via HMMA.  Epilogue: Q fp32; K fp16 single; V fp16 single (T).
// ---------------------------------------------------------------------------
__global__ void __launch_bounds__(256, 2)
gemm_qkv_mma(const float* __restrict__ bq, const float* __restrict__ bk,
             const float* __restrict__ bv)
{
    const int mode = blockIdx.z;
    const int m0 = blockIdx.y * 128, n0 = blockIdx.x * 64;
    const float* bias = (mode == 0) ? bq : (mode == 1) ? bk : bv;

    float c[2][4][4];
    gemm_core(g_Xh, g_Xl, g_Wh + (size_t)mode * WSZ, g_Wl + (size_t)mode * WSZ, m0, n0, c);

    const int tid = threadIdx.x, wid = tid >> 5, lane = tid & 31;
    const int wr = wid >> 1, wc = wid & 1, g = lane >> 2, tg = lane & 3;

#pragma unroll
    for (int mt = 0; mt < 2; mt++) {
#pragma unroll
        for (int nt = 0; nt < 4; nt++) {
            int n = n0 + wc * 32 + nt * 8 + tg * 2;
            int h = n >> 6, dh = n & 63;
            float b0v = bias[n], b1v = bias[n + 1];
#pragma unroll
            for (int e = 0; e < 2; e++) {
                int m = m0 + wr * 32 + mt * 16 + g + e * 8;
                int b = m >> 12, t = m & 4095;
                float v0 = c[mt][nt][e * 2 + 0] + b0v;
                float v1 = c[mt][nt][e * 2 + 1] + b1v;
                size_t bhh = (size_t)b * HH + h;
                if (mode == 0) {
                    *(float2*)&g_Q[(bhh * TT + t) * DHH + dh] = make_float2(v0, v1);
                } else if (mode == 1) {
                    size_t idx = (bhh * TT + t) * DHH + dh;
                    *(uint32_t*)&g_Kh[idx] = pack_f16x2(v0, v1);
                } else {
                    size_t i0 = (bhh * DHH + dh) * TT + t;
                    size_t i1 = (bhh * DHH + dh + 1) * TT + t;
                    g_Vth[i0] = __float2half_rn(v0);
                    g_Vth[i1] = __float2half_rn(v1);
                }
            }
        }
    }
}

// ---------------------------------------------------------------------------
// Output projection via HMMA (unchanged, validated round 9)
// ---------------------------------------------------------------------------
__global__ void __launch_bounds__(256, 2)
gemm_out_mma(const float* __restrict__ bo, float* __restrict__ out)
{
    const int m0 = blockIdx.y * 128, n0 = blockIdx.x * 64;
    float c[2][4][4];
    gemm_core(g_Oh, g_Ol, g_Wh + 3 * (size_t)WSZ, g_Wl + 3 * (size_t)WSZ, m0, n0, c);

    const int tid = threadIdx.x, wid = tid >> 5, lane = tid & 31;
    const int wr = wid >> 1, wc = wid & 1, g = lane >> 2, tg = lane & 3;

#pragma unroll
    for (int mt = 0; mt < 2; mt++) {
#pragma unroll
        for (int nt = 0; nt < 4; nt++) {
            int n = n0 + wc * 32 + nt * 8 + tg * 2;
            float b0v = bo[n], b1v = bo[n + 1];
#pragma unroll
            for (int e = 0; e < 2; e++) {
                int m = m0 + wr * 32 + mt * 16 + g + e * 8;
                float v0 = c[mt][nt][e * 2 + 0] + b0v;
                float v1 = c[mt][nt][e * 2 + 1] + b1v;
                *(float2*)&out[(size_t)m * DD + n] = make_float2(v0, v1);
            }
        }
    }
}

// ---------------------------------------------------------------------------
// Kernel: flash attention.  BM=128, 4 warps, 32 q-rows per warp (2 m-tiles):
// each K/V fragment load feeds TWO MMAs -> fragment L1 traffic per output
// halves vs round 16.  fp16 numerics identical to round 16.
// Grid (16, 32).  smem 18.4 KB.  2 CTAs/SM.
// ---------------------------------------------------------------------------
#define SROW 72   // smem row stride (fp16 units)

__global__ void __launch_bounds__(128, 2)
flash_attn_mma(int dummy)
{
    __shared__ __half sKh[64 * SROW];
    __shared__ __half sVh[64 * SROW];   // [dh][key]

    const int tid  = threadIdx.x;
    const int wid  = tid >> 5;
    const int lane = tid & 31;
    const int g    = lane >> 2;      // group row 0..7
    const int tg   = lane & 3;       // thread-in-group 0..3
    const int bh   = blockIdx.x;     // 0..15
    const int q0   = blockIdx.y * 128;
    const int r0   = q0 + wid * 32;  // this warp's first q row (32 rows)

    const __half* gKh = g_Kh + (size_t)bh * TT * DHH;
    const __half* gVh = g_Vth + (size_t)bh * DHH * TT;

    // ---- load Q A-fragments for both m-tiles (fp16), scaled by 1/8 ----
    uint32_t qa[2][4][4];   // [mtile][ks][reg]
#pragma unroll
    for (int mt = 0; mt < 2; mt++) {
        const float* q0p = g_Q + ((size_t)bh * TT + r0 + mt * 16 + g) * DHH;
        const float* q8p = q0p + 8 * DHH;
#pragma unroll
        for (int ks = 0; ks < 4; ks++) {
            int c0 = ks * 16 + tg * 2;
            int c1 = c0 + 8;
            float2 v00 = *(const float2*)(q0p + c0);
            float2 v10 = *(const float2*)(q8p + c0);
            float2 v01 = *(const float2*)(q0p + c1);
            float2 v11 = *(const float2*)(q8p + c1);
            qa[mt][ks][0] = pack_f16x2(v00.x * 0.125f, v00.y * 0.125f);
            qa[mt][ks][1] = pack_f16x2(v10.x * 0.125f, v10.y * 0.125f);
            qa[mt][ks][2] = pack_f16x2(v01.x * 0.125f, v01.y * 0.125f);
            qa[mt][ks][3] = pack_f16x2(v11.x * 0.125f, v11.y * 0.125f);
        }
    }

    // mask rows: r0+g, r0+g+8, r0+g+16, r0+g+24
    const uint64_t* mr0  = g_maskbits + (size_t)(r0 + g) * 64;
    const uint64_t* mr8  = mr0 + 8 * 64;
    const uint64_t* mr16 = mr0 + 16 * 64;
    const uint64_t* mr24 = mr0 + 24 * 64;

    float o[2][8][4];
#pragma unroll
    for (int mt = 0; mt < 2; mt++)
#pragma unroll
        for (int nt = 0; nt < 8; nt++)
#pragma unroll
            for (int i = 0; i < 4; i++) o[mt][nt][i] = 0.f;
    float l0 = 0.f, l1 = 0.f, l2 = 0.f, l3 = 0.f;

    for (int kt = 0; kt < TT / 64; kt++) {
        const int k0 = kt * 64;
        __syncthreads();   // previous tile's fragment reads done before overwrite

        // ---- stage K and V^T (row-major, pad SROW): 2 arrays x 512 chunks ----
#pragma unroll
        for (int it = 0; it < 2; it++) {
            int slot = tid + it * 128;        // 0..255
            int arr = slot >> 7;              // 0:Kh 1:Vh
            int rem = slot & 127;
            int r = rem >> 1, jbase = (rem & 1) * 4;
#pragma unroll
            for (int j = 0; j < 4; j++) {
                int c8 = jbase + j;
                if (arr == 0)
                    *(uint4*)&sKh[r * SROW + c8 * 8] = *(const uint4*)(gKh + (size_t)(k0 + r) * DHH + c8 * 8);
                else
                    *(uint4*)&sVh[r * SROW + c8 * 8] = *(const uint4*)(gVh + (size_t)r * TT + k0 + c8 * 8);
            }
        }
        __syncthreads();

        const uint64_t m0  = mr0[kt];
        const uint64_t m8  = mr8[kt];
        const uint64_t m16 = mr16[kt];
        const uint64_t m24 = mr24[kt];

        // ---- fused S + exp per nt (keeps s live range small) ----
        uint32_t pa0[4][4], pa1[4][4];    // P A-fragments per m-tile
#pragma unroll
        for (int nt = 0; nt < 8; nt++) {
            float s0[4] = {0.f, 0.f, 0.f, 0.f};
            float s1[4] = {0.f, 0.f, 0.f, 0.f};
            const __half* rKh = &sKh[(nt * 8 + g) * SROW];
#pragma unroll
            for (int ks = 0; ks < 4; ks++) {
                int kk = ks * 16 + tg * 2;
                uint32_t bh0 = *(const uint32_t*)&rKh[kk];
                uint32_t bh1 = *(const uint32_t*)&rKh[kk + 8];
                mma16816h(s0, qa[0][ks], bh0, bh1);
                mma16816h(s1, qa[1][ks], bh0, bh1);
            }
            int cb = nt * 8 + tg * 2;
            float p0 = ((m0 >> cb) & 1ull)        ? __expf(s0[0]) : 0.f;
            float p1 = ((m0 >> (cb + 1)) & 1ull)  ? __expf(s0[1]) : 0.f;
            float p2 = ((m8 >> cb) & 1ull)        ? __expf(s0[2]) : 0.f;
            float p3 = ((m8 >> (cb + 1)) & 1ull)  ? __expf(s0[3]) : 0.f;
            float p4 = ((m16 >> cb) & 1ull)       ? __expf(s1[0]) : 0.f;
            float p5 = ((m16 >> (cb + 1)) & 1ull) ? __expf(s1[1]) : 0.f;
            float p6 = ((m24 >> cb) & 1ull)       ? __expf(s1[2]) : 0.f;
            float p7 = ((m24 >> (cb + 1)) & 1ull) ? __expf(s1[3]) : 0.f;
            l0 += p0 + p1;
            l1 += p2 + p3;
            l2 += p4 + p5;
            l3 += p6 + p7;
            int ks = nt >> 1;
            int hi = (nt & 1) ? 2 : 0;
            pa0[ks][hi]     = pack_f16x2(p0, p1);
            pa0[ks][hi + 1] = pack_f16x2(p2, p3);
            pa1[ks][hi]     = pack_f16x2(p4, p5);
            pa1[ks][hi + 1] = pack_f16x2(p6, p7);
        }

        // ---- O += P Vh (both m-tiles share each V fragment) ----
#pragma unroll
        for (int nt = 0; nt < 8; nt++) {
            const __half* rVh = &sVh[(nt * 8 + g) * SROW];
#pragma unroll
            for (int ks = 0; ks < 4; ks++) {
                int kk = ks * 16 + tg * 2;
                uint32_t vh0 = *(const uint32_t*)&rVh[kk];
                uint32_t vh1 = *(const uint32_t*)&rVh[kk + 8];
                mma16816h(o[0][nt], pa0[ks], vh0, vh1);
                mma16816h(o[1][nt], pa1[ks], vh0, vh1);
            }
        }
    }

    // ---- epilogue: reduce l, normalize, split bf16, store packed (b,t,D) ----
    l0 += __shfl_xor_sync(0xffffffffu, l0, 1);
    l0 += __shfl_xor_sync(0xffffffffu, l0, 2);
    l1 += __shfl_xor_sync(0xffffffffu, l1, 1);
    l1 += __shfl_xor_sync(0xffffffffu, l1, 2);
    l2 += __shfl_xor_sync(0xffffffffu, l2, 1);
    l2 += __shfl_xor_sync(0xffffffffu, l2, 2);
    l3 += __shfl_xor_sync(0xffffffffu, l3, 1);
    l3 += __shfl_xor_sync(0xffffffffu, l3, 2);
    float inv[4] = {1.f / l0, 1.f / l1, 1.f / l2, 1.f / l3};

    const int b = bh >> 3, h = bh & 7;
#pragma unroll
    for (int mt = 0; mt < 2; mt++) {
        size_t baseA = ((size_t)b * TT + (r0 + mt * 16 + g)) * DD + h * DHH;
        size_t baseB = baseA + (size_t)8 * DD;
        float invA = inv[mt * 2], invB = inv[mt * 2 + 1];
#pragma unroll
        for (int nt = 0; nt < 8; nt++) {
            int c = nt * 8 + tg * 2;
            float v0 = o[mt][nt][0] * invA, v1 = o[mt][nt][1] * invA;
            float v2 = o[mt][nt][2] * invB, v3 = o[mt][nt][3] * invB;
            float h0 = bf16_round(v0), h1 = bf16_round(v1);
            float h2 = bf16_round(v2), h3 = bf16_round(v3);
            *(uint32_t*)&g_Oh[baseA + c] = pack_bf16x2(h0, h1);
            *(uint32_t*)&g_Ol[baseA + c] = pack_bf16x2(v0 - h0, v1 - h1);
            *(uint32_t*)&g_Oh[baseB + c] = pack_bf16x2(h2, h3);
            *(uint32_t*)&g_Ol[baseB + c] = pack_bf16x2(v2 - h2, v3 - h3);
        }
    }
}

// ---------------------------------------------------------------------------
// Launch.  Inputs identified BY SIZE.
// ---------------------------------------------------------------------------
extern "C" void kernel_launch(void* const* d_in, const int* in_sizes, int n_in,
                              void* d_out, int out_size)
{
    const float* x = nullptr;
    const float* Ws[4] = {nullptr, nullptr, nullptr, nullptr};
    const float* bs[4] = {nullptr, nullptr, nullptr, nullptr};
    const void*  mask = nullptr;
    int wc = 0, bc = 0;
    for (int i = 0; i < n_in; i++) {
        int sz = in_sizes[i];
        if (sz == TT * TT)            mask = d_in[i];
        else if (sz == MTOT * DD)     x = (const float*)d_in[i];
        else if (sz == DD * DD)       { if (wc < 4) Ws[wc++] = (const float*)d_in[i]; }
        else if (sz == DD)            { if (bc < 4) bs[bc++] = (const float*)d_in[i]; }
    }
    float* out = (float*)d_out;

    cudaFuncSetAttribute(gemm_qkv_mma, cudaFuncAttributeMaxDynamicSharedMemorySize, GEMM_SMEM);
    cudaFuncSetAttribute(gemm_out_mma, cudaFuncAttributeMaxDynamicSharedMemorySize, GEMM_SMEM);

    pack_mask_kernel<<<1024, 256>>>(mask);
    split_all_kernel<<<(MTOT * DD + 4 * WSZ) / 1024, 256>>>(x, Ws[0], Ws[1], Ws[2], Ws[3]);
    gemm_qkv_mma<<<dim3(DD / 64, MTOT / 128, 3), 256, GEMM_SMEM>>>(bs[0], bs[1], bs[2]);
    flash_attn_mma<<<dim3(BB * HH, TT / 128), 128>>>(0);
    gemm_out_mma<<<dim3(DD / 64, MTOT / 128), 256, GEMM_SMEM>>>(bs[3], out);
}